// round 1
// baseline (speedup 1.0000x reference)
#include <cuda_runtime.h>
#include <math.h>
#include <stddef.h>

// ---------------- problem constants ----------------
#define NS   4096
#define NG   20000
#define NE   131072
#define DIN  256
#define H    4
#define C1   64
#define C3   128
#define HC1  256   // H*C1
#define HC3  512   // H*C3

// ---------------- device scratch (static, no runtime alloc) ----------------
__device__ float g_xl_sg[NS * HC1];     // layer1 sg: transformed sources (samples)
__device__ float g_xr_sg[NG * HC1];     // layer1 sg: transformed targets (genes)
__device__ float g_xl_gs[NG * HC1];     // layer1 gs: transformed sources (genes)
__device__ float g_xr_gs[NS * HC1];     // layer1 gs: transformed targets (samples)
__device__ float g_x1_gene[NG * HC1];   // elu output layer1 genes
__device__ float g_x1_sample[NS * HC1]; // elu output layer1 samples
__device__ float g_sl1[NS * C1];        // self-loop linear layer1
__device__ float g_xl3[NG * HC3];       // layer3 xl
__device__ float g_xr3[NS * HC3];       // layer3 xr
__device__ float g_agg3[NS * HC3];      // layer3 per-head aggregate
__device__ float g_sl3[NS * C3];        // self-loop linear layer3
__device__ float g_alpha[NE * H];       // per-edge attention logits (reused)

__device__ int g_deg[NG];               // degree scratch (max of NG, NS)
__device__ int g_off_sg[NG + 1];
__device__ int g_cur_sg[NG];
__device__ int g_eid_sg[NE];
__device__ int g_off_gs[NS + 1];
__device__ int g_cur_gs[NS];
__device__ int g_eid_gs[NE];

// ---------------- SGEMM: C = A[M,K] @ W[K,N] + bias[N] ----------------
// BM=64, BN=64, BK=16, 256 threads, 4x4 per thread. K multiple of 16,
// N multiple of 64 (true here: 64/128/256/512). M guarded.
#define BM 64
#define BN 64
#define BK 16

__global__ void sgemm_bias(const float* __restrict__ A, const float* __restrict__ W,
                           const float* __restrict__ bias, float* __restrict__ C,
                           int M, int N, int K) {
    __shared__ float As[BK][BM + 4];   // pitch 68 floats (16B aligned rows)
    __shared__ float Bs[BK][BN + 4];

    int tid = threadIdx.x;            // 0..255
    int tx = tid & 15;                // 0..15
    int ty = tid >> 4;                // 0..15
    int row0 = blockIdx.y * BM;
    int col0 = blockIdx.x * BN;

    float acc[4][4] = {};

    for (int k0 = 0; k0 < K; k0 += BK) {
        // load A tile: 64 rows x 16 k, one float4 per thread
        {
            int m  = tid >> 2;
            int k4 = (tid & 3) * 4;
            int row = row0 + m;
            float4 v = make_float4(0.f, 0.f, 0.f, 0.f);
            if (row < M) v = *(const float4*)(A + (size_t)row * K + k0 + k4);
            As[k4 + 0][m] = v.x;
            As[k4 + 1][m] = v.y;
            As[k4 + 2][m] = v.z;
            As[k4 + 3][m] = v.w;
        }
        // load B tile: 16 k x 64 n, one float4 per thread
        {
            int k  = tid >> 4;
            int n4 = (tid & 15) * 4;
            float4 v = *(const float4*)(W + (size_t)(k0 + k) * N + col0 + n4);
            *(float4*)&Bs[k][n4] = v;
        }
        __syncthreads();

        #pragma unroll
        for (int kk = 0; kk < BK; kk++) {
            float4 a4 = *(const float4*)&As[kk][ty * 4];
            float4 b4 = *(const float4*)&Bs[kk][tx * 4];
            float a[4] = {a4.x, a4.y, a4.z, a4.w};
            float b[4] = {b4.x, b4.y, b4.z, b4.w};
            #pragma unroll
            for (int i = 0; i < 4; i++)
                #pragma unroll
                for (int j = 0; j < 4; j++)
                    acc[i][j] = fmaf(a[i], b[j], acc[i][j]);
        }
        __syncthreads();
    }

    float4 bv = *(const float4*)(bias + col0 + tx * 4);
    #pragma unroll
    for (int i = 0; i < 4; i++) {
        int row = row0 + ty * 4 + i;
        if (row < M) {
            float4 o;
            o.x = acc[i][0] + bv.x;
            o.y = acc[i][1] + bv.y;
            o.z = acc[i][2] + bv.z;
            o.w = acc[i][3] + bv.w;
            *(float4*)(C + (size_t)row * N + col0 + tx * 4) = o;
        }
    }
}

// ---------------- CSR build ----------------
__global__ void count_kernel(const int* __restrict__ dst, int* __restrict__ deg, int E) {
    int e = blockIdx.x * blockDim.x + threadIdx.x;
    if (e < E) atomicAdd(&deg[dst[e]], 1);
}

// single-block exclusive scan (n up to 20000)
__global__ void scan_kernel(const int* __restrict__ deg, int* __restrict__ off, int n) {
    __shared__ int sh[1024];
    int tid = threadIdx.x;
    int carry = 0;
    for (int base = 0; base < n; base += 1024) {
        int i = base + tid;
        int v = (i < n) ? deg[i] : 0;
        __syncthreads();
        sh[tid] = v;
        __syncthreads();
        for (int s = 1; s < 1024; s <<= 1) {
            int t = (tid >= s) ? sh[tid - s] : 0;
            __syncthreads();
            sh[tid] += t;
            __syncthreads();
        }
        if (i < n) off[i] = carry + sh[tid] - v;   // exclusive
        carry += sh[1023];
    }
    if (tid == 0) off[n] = carry;
}

__global__ void scatter_kernel(const int* __restrict__ dst, int* __restrict__ cur,
                               int* __restrict__ eid, int E) {
    int e = blockIdx.x * blockDim.x + threadIdx.x;
    if (e < E) {
        int p = atomicAdd(&cur[dst[e]], 1);
        eid[p] = e;
    }
}

// ---------------- per-edge attention logits ----------------
// warp per (edge, head): alpha[e,h] = sum_c lrelu(xl[src,h,c]+xr[dst,h,c]) * att[h,c]
template <int C>
__global__ void alpha_kernel(const int* __restrict__ src, const int* __restrict__ dst,
                             const float* __restrict__ xl, const float* __restrict__ xr,
                             const float* __restrict__ att, float* __restrict__ alpha, int E) {
    int w = (blockIdx.x * blockDim.x + threadIdx.x) >> 5;
    int lane = threadIdx.x & 31;
    if (w >= E * H) return;
    int e = w >> 2;
    int h = w & 3;
    int s = src[e];
    int d = dst[e];
    const float* pl = xl + ((size_t)s * H + h) * C;
    const float* pr = xr + ((size_t)d * H + h) * C;
    const float* pa = att + h * C;
    float sum = 0.f;
    if (C == 64) {
        float2 a = *(const float2*)(pl + 2 * lane);
        float2 b = *(const float2*)(pr + 2 * lane);
        float2 t = *(const float2*)(pa + 2 * lane);
        float g0 = a.x + b.x; g0 = g0 > 0.f ? g0 : 0.2f * g0;
        float g1 = a.y + b.y; g1 = g1 > 0.f ? g1 : 0.2f * g1;
        sum = fmaf(g0, t.x, g1 * t.y);
    } else {  // C == 128
        float4 a = *(const float4*)(pl + 4 * lane);
        float4 b = *(const float4*)(pr + 4 * lane);
        float4 t = *(const float4*)(pa + 4 * lane);
        float g0 = a.x + b.x; g0 = g0 > 0.f ? g0 : 0.2f * g0;
        float g1 = a.y + b.y; g1 = g1 > 0.f ? g1 : 0.2f * g1;
        float g2 = a.z + b.z; g2 = g2 > 0.f ? g2 : 0.2f * g2;
        float g3 = a.w + b.w; g3 = g3 > 0.f ? g3 : 0.2f * g3;
        sum = g0 * t.x + g1 * t.y + g2 * t.z + g3 * t.w;
    }
    #pragma unroll
    for (int o = 16; o; o >>= 1) sum += __shfl_xor_sync(0xFFFFFFFFu, sum, o);
    if (lane == 0) alpha[e * H + h] = sum;
}

// ---------------- segment softmax + aggregation ----------------
// warp per (dst, head). Contention-free via CSR. Optionally fuses
// bias + self-loop add + ELU epilogue (layer 1). Layer 3 writes raw per-head.
template <int C, bool FINAL>
__global__ void aggregate_kernel(const int* __restrict__ off, const int* __restrict__ eid,
                                 const int* __restrict__ src,
                                 const float* __restrict__ xl, const float* __restrict__ alpha,
                                 const float* __restrict__ bias, const float* __restrict__ self,
                                 float* __restrict__ out, int Nd) {
    int w = (blockIdx.x * blockDim.x + threadIdx.x) >> 5;
    int lane = threadIdx.x & 31;
    if (w >= Nd * H) return;
    int d = w >> 2;
    int h = w & 3;
    int b0 = off[d], b1 = off[d + 1];

    float m = -1e30f;
    for (int i = b0; i < b1; i++) m = fmaxf(m, alpha[eid[i] * H + h]);

    constexpr int V = C / 32;   // 2 or 4
    float acc[V] = {};
    float den = 0.f;
    for (int i = b0; i < b1; i++) {
        int e = eid[i];
        float a = expf(alpha[e * H + h] - m);
        den += a;
        const float* p = xl + ((size_t)src[e] * H + h) * C + lane * V;
        if (V == 2) {
            float2 t = *(const float2*)p;
            acc[0] = fmaf(a, t.x, acc[0]);
            acc[1] = fmaf(a, t.y, acc[1]);
        } else {
            float4 t = *(const float4*)p;
            acc[0] = fmaf(a, t.x, acc[0]);
            acc[1] = fmaf(a, t.y, acc[1]);
            acc[2] = fmaf(a, t.z, acc[2]);
            acc[3] = fmaf(a, t.w, acc[3]);
        }
    }
    float inv = 1.f / (den + 1e-16f);
    float* po = out + ((size_t)d * H + h) * C + lane * V;
    #pragma unroll
    for (int v = 0; v < V; v++) {
        float x = acc[v] * inv;
        if (FINAL) {
            x += bias[h * C + lane * V + v];
            if (self) x += self[(size_t)d * C + lane * V + v];
            x = x > 0.f ? x : (expf(x) - 1.f);
        }
        po[v] = x;
    }
}

// ---------------- layer-3 finalize: head mean + bias + self + ELU ----------------
__global__ void finalize3_kernel(const float* __restrict__ agg, const float* __restrict__ bias3,
                                 const float* __restrict__ sl3, float* __restrict__ out) {
    int i = blockIdx.x * blockDim.x + threadIdx.x;
    if (i >= NS * C3) return;
    int d = i >> 7;
    int c = i & 127;
    const float* p = agg + (size_t)d * HC3;
    float s = 0.25f * (p[c] + p[C3 + c] + p[2 * C3 + c] + p[3 * C3 + c]);
    float x = s + bias3[c] + sl3[i];
    out[i] = x > 0.f ? x : (expf(x) - 1.f);
}

// ---------------- host launch ----------------
static inline float* sym(const void* s) {
    void* p = nullptr;
    cudaGetSymbolAddress(&p, s);
    return (float*)p;
}
static inline int* symi(const void* s) {
    void* p = nullptr;
    cudaGetSymbolAddress(&p, s);
    return (int*)p;
}

extern "C" void kernel_launch(void* const* d_in, const int* in_sizes, int n_in,
                              void* d_out, int out_size) {
    const float* x_sample = (const float*)d_in[0];
    const float* x_gene   = (const float*)d_in[1];
    const int*   sg_src   = (const int*)d_in[2];
    const int*   sg_dst   = (const int*)d_in[3];
    const int*   gs_src   = (const int*)d_in[4];
    const int*   gs_dst   = (const int*)d_in[5];
    const float* Wl1_sg = (const float*)d_in[6];
    const float* bl1_sg = (const float*)d_in[7];
    const float* Wr1_sg = (const float*)d_in[8];
    const float* br1_sg = (const float*)d_in[9];
    const float* att1_sg  = (const float*)d_in[10];
    const float* bias1_sg = (const float*)d_in[11];
    const float* Wl1_gs = (const float*)d_in[12];
    const float* bl1_gs = (const float*)d_in[13];
    const float* Wr1_gs = (const float*)d_in[14];
    const float* br1_gs = (const float*)d_in[15];
    const float* att1_gs  = (const float*)d_in[16];
    const float* bias1_gs = (const float*)d_in[17];
    const float* Wl3_gs = (const float*)d_in[18];
    const float* bl3_gs = (const float*)d_in[19];
    const float* Wr3_gs = (const float*)d_in[20];
    const float* br3_gs = (const float*)d_in[21];
    const float* att3_gs  = (const float*)d_in[22];
    const float* bias3_gs = (const float*)d_in[23];
    const float* sl1_W = (const float*)d_in[24];
    const float* sl1_b = (const float*)d_in[25];
    const float* sl3_W = (const float*)d_in[26];
    const float* sl3_b = (const float*)d_in[27];
    float* out = (float*)d_out;

    float* xl_sg = sym(g_xl_sg);
    float* xr_sg = sym(g_xr_sg);
    float* xl_gs = sym(g_xl_gs);
    float* xr_gs = sym(g_xr_gs);
    float* x1_gene = sym(g_x1_gene);
    float* x1_sample = sym(g_x1_sample);
    float* sl1 = sym(g_sl1);
    float* xl3 = sym(g_xl3);
    float* xr3 = sym(g_xr3);
    float* agg3 = sym(g_agg3);
    float* sl3 = sym(g_sl3);
    float* alpha = sym(g_alpha);
    int* deg = symi(g_deg);
    int* off_sg = symi(g_off_sg);
    int* cur_sg = symi(g_cur_sg);
    int* eid_sg = symi(g_eid_sg);
    int* off_gs = symi(g_off_gs);
    int* cur_gs = symi(g_cur_gs);
    int* eid_gs = symi(g_eid_gs);

    dim3 tb(256);
    int eb = (NE + 255) / 256;

    // ----- CSR build for sg (dst = gene) and gs (dst = sample) -----
    cudaMemsetAsync(deg, 0, NG * sizeof(int));
    count_kernel<<<eb, tb>>>(sg_dst, deg, NE);
    scan_kernel<<<1, 1024>>>(deg, off_sg, NG);
    cudaMemcpyAsync(cur_sg, off_sg, NG * sizeof(int), cudaMemcpyDeviceToDevice);
    scatter_kernel<<<eb, tb>>>(sg_dst, cur_sg, eid_sg, NE);

    cudaMemsetAsync(deg, 0, NS * sizeof(int));
    count_kernel<<<eb, tb>>>(gs_dst, deg, NE);
    scan_kernel<<<1, 1024>>>(deg, off_gs, NS);
    cudaMemcpyAsync(cur_gs, off_gs, NS * sizeof(int), cudaMemcpyDeviceToDevice);
    scatter_kernel<<<eb, tb>>>(gs_dst, cur_gs, eid_gs, NE);

    // ----- layer 1: sg (sample -> gene) -----
    sgemm_bias<<<dim3(HC1 / BN, (NS + BM - 1) / BM), tb>>>(x_sample, Wl1_sg, bl1_sg, xl_sg, NS, HC1, DIN);
    sgemm_bias<<<dim3(HC1 / BN, (NG + BM - 1) / BM), tb>>>(x_gene, Wr1_sg, br1_sg, xr_sg, NG, HC1, DIN);
    alpha_kernel<C1><<<(NE * H + 7) / 8, tb>>>(sg_src, sg_dst, xl_sg, xr_sg, att1_sg, alpha, NE);
    aggregate_kernel<C1, true><<<(NG * H + 7) / 8, tb>>>(off_sg, eid_sg, sg_src, xl_sg, alpha,
                                                         bias1_sg, nullptr, x1_gene, NG);

    // ----- layer 1: gs (gene -> sample) + self loop -----
    sgemm_bias<<<dim3(HC1 / BN, (NG + BM - 1) / BM), tb>>>(x_gene, Wl1_gs, bl1_gs, xl_gs, NG, HC1, DIN);
    sgemm_bias<<<dim3(HC1 / BN, (NS + BM - 1) / BM), tb>>>(x_sample, Wr1_gs, br1_gs, xr_gs, NS, HC1, DIN);
    sgemm_bias<<<dim3(C1 / BN, (NS + BM - 1) / BM), tb>>>(x_sample, sl1_W, sl1_b, sl1, NS, C1, DIN);
    alpha_kernel<C1><<<(NE * H + 7) / 8, tb>>>(gs_src, gs_dst, xl_gs, xr_gs, att1_gs, alpha, NE);
    aggregate_kernel<C1, true><<<(NS * H + 7) / 8, tb>>>(off_gs, eid_gs, gs_src, xl_gs, alpha,
                                                         bias1_gs, sl1, x1_sample, NS);

    // ----- layer 3: gs (gene -> sample), concat=False (head mean) -----
    sgemm_bias<<<dim3(HC3 / BN, (NG + BM - 1) / BM), tb>>>(x1_gene, Wl3_gs, bl3_gs, xl3, NG, HC3, DIN);
    sgemm_bias<<<dim3(HC3 / BN, (NS + BM - 1) / BM), tb>>>(x1_sample, Wr3_gs, br3_gs, xr3, NS, HC3, DIN);
    sgemm_bias<<<dim3(C3 / BN, (NS + BM - 1) / BM), tb>>>(x1_sample, sl3_W, sl3_b, sl3, NS, C3, DIN);
    alpha_kernel<C3><<<(NE * H + 7) / 8, tb>>>(gs_src, gs_dst, xl3, xr3, att3_gs, alpha, NE);
    aggregate_kernel<C3, false><<<(NS * H + 7) / 8, tb>>>(off_gs, eid_gs, gs_src, xl3, alpha,
                                                          nullptr, nullptr, agg3, NS);
    finalize3_kernel<<<(NS * C3 + 255) / 256, tb>>>(agg3, bias3_gs, sl3, out);
}

// round 3
// speedup vs baseline: 1.0541x; 1.0541x over previous
#include <cuda_runtime.h>
#include <mma.h>
#include <math.h>
#include <stddef.h>
#include <stdint.h>

using namespace nvcuda;

// ---------------- problem constants ----------------
#define NS   4096
#define NG   20000
#define NGP  20096   // padded to multiple of 128
#define NE   131072
#define DIN  256
#define H    4
#define C1   64
#define C3   128
#define HC1  256
#define HC3  512

// ---------------- device scratch (static, no runtime alloc) ----------------
__device__ __align__(128) float g_xl_sg[NS * HC1];
__device__ __align__(128) float g_xr_sg[NGP * HC1];
__device__ __align__(128) float g_xl_gs[NGP * HC1];
__device__ __align__(128) float g_xr_gs[NS * HC1];
__device__ __align__(128) float g_x1_gene[NG * HC1];
__device__ __align__(128) float g_x1_sample[NS * HC1];
__device__ __align__(128) float g_sl1[NS * C1];
__device__ __align__(128) float g_xl3[NGP * HC3];
__device__ __align__(128) float g_xr3[NS * HC3];
__device__ __align__(128) float g_sl3[NS * C3];
__device__ __align__(128) float g_w5p[DIN * 128];   // sl1_W padded to 128 cols

__device__ int g_deg[NG];
__device__ int g_off_sg[NG + 1];
__device__ int g_cur_sg[NG];
__device__ int g_eid_sg[NE];
__device__ int g_off_gs[NS + 1];
__device__ int g_cur_gs[NS];
__device__ int g_eid_gs[NE];

// ---------------- helpers ----------------
__device__ __forceinline__ uint32_t smem_u32(const void* p) {
    uint32_t a;
    asm("{ .reg .u64 t; cvta.to.shared.u64 t, %1; cvt.u32.u64 %0, t; }" : "=r"(a) : "l"(p));
    return a;
}
#define CP_ASYNC16(dst, src) \
    asm volatile("cp.async.ca.shared.global [%0], [%1], 16;" :: "r"(dst), "l"(src))
#define CP_COMMIT() asm volatile("cp.async.commit_group;")
#define CP_WAIT(n)  asm volatile("cp.async.wait_group %0;" :: "n"(n))

// ---------------- pad sl1_W [256,64] -> [256,128] (zero-pad cols) ----------------
__global__ void pad_w_kernel(const float* __restrict__ W, float* __restrict__ WP, int N) {
    int i = blockIdx.x * blockDim.x + threadIdx.x;
    if (i < DIN * 128) {
        int k = i >> 7, c = i & 127;
        WP[i] = (c < N) ? W[k * N + c] : 0.f;
    }
}

// ---------------- WMMA tf32 GEMM: C[M,Nout] = A[M,256] @ B[256,ldB](cols) + bias ----------------
// 256 threads, 8 warps (4 m x 2 n), block tile 128x128, BK=32, A double-buffered
// via cp.async; B fragments loaded directly from global (L2-resident weights).
// C rows are stored unguarded: all C buffers are padded to gridDim.y*128 rows.
#define GEMM_THREADS 256
#define GEMM_SMEM 67584   // max(2*128*40, 128*132) floats * 4

__global__ void __launch_bounds__(GEMM_THREADS) gemm_wmma(
    const float* __restrict__ A, const float* __restrict__ B, int ldB,
    const float* __restrict__ bias, float* __restrict__ C, int M, int Nout) {
    extern __shared__ float sm[];
    constexpr int K = 256;
    const int tid = threadIdx.x;
    const int wid = tid >> 5;
    const int warp_m = wid >> 1;     // 0..3
    const int warp_n = wid & 1;      // 0..1
    const int m0 = blockIdx.y * 128;
    const int col0 = blockIdx.x * 128;

    wmma::fragment<wmma::accumulator, 16, 16, 8, float> cfr[2][4];
    #pragma unroll
    for (int i = 0; i < 2; i++)
        #pragma unroll
        for (int t = 0; t < 4; t++) wmma::fill_fragment(cfr[i][t], 0.f);

    // A tile loader: 128 rows x 32 k into buffer b (row pitch 40 floats)
    auto loadA = [&](int s, int b) {
        const float* Ab = A + (size_t)m0 * K + s * 32;
        float* dst = sm + b * 5120;
        #pragma unroll
        for (int i = 0; i < 4; i++) {
            int ch = tid + i * 256;
            int r = ch >> 3, c4 = ch & 7;
            float* dp = dst + r * 40 + c4 * 4;
            if (m0 + r < M) {
                CP_ASYNC16(smem_u32(dp), Ab + (size_t)r * K + c4 * 4);
            } else {
                *(float4*)dp = make_float4(0.f, 0.f, 0.f, 0.f);
            }
        }
    };

    loadA(0, 0);
    CP_COMMIT();

    #pragma unroll 1
    for (int s = 0; s < 8; s++) {
        int b = s & 1;
        if (s < 7) { loadA(s + 1, b ^ 1); CP_COMMIT(); }
        if (s < 7) { CP_WAIT(1); } else { CP_WAIT(0); }
        __syncthreads();

        const float* As = sm + b * 5120 + warp_m * 32 * 40;
        #pragma unroll
        for (int kk = 0; kk < 4; kk++) {
            wmma::fragment<wmma::matrix_a, 16, 16, 8, wmma::precision::tf32, wmma::row_major> af[2];
            wmma::load_matrix_sync(af[0], As + kk * 8, 40);
            wmma::load_matrix_sync(af[1], As + 16 * 40 + kk * 8, 40);
            #pragma unroll
            for (int i = 0; i < 2; i++)
                #pragma unroll
                for (int e = 0; e < af[i].num_elements; e++)
                    af[i].x[e] = wmma::__float_to_tf32(af[i].x[e]);
            #pragma unroll
            for (int t = 0; t < 4; t++) {
                wmma::fragment<wmma::matrix_b, 16, 16, 8, wmma::precision::tf32, wmma::row_major> bf;
                const float* Bp = B + (size_t)(s * 32 + kk * 8) * ldB + col0 + warp_n * 64 + t * 16;
                wmma::load_matrix_sync(bf, Bp, ldB);
                #pragma unroll
                for (int e = 0; e < bf.num_elements; e++)
                    bf.x[e] = wmma::__float_to_tf32(bf.x[e]);
                wmma::mma_sync(cfr[0][t], af[0], bf, cfr[0][t]);
                wmma::mma_sync(cfr[1][t], af[1], bf, cfr[1][t]);
            }
        }
        __syncthreads();
    }

    // epilogue: stage to smem (pitch 132), then copy out with bias + col guard
    float* stg = sm;
    #pragma unroll
    for (int i = 0; i < 2; i++)
        #pragma unroll
        for (int t = 0; t < 4; t++)
            wmma::store_matrix_sync(stg + (warp_m * 32 + i * 16) * 132 + warp_n * 64 + t * 16,
                                    cfr[i][t], 132, wmma::mem_row_major);
    __syncthreads();

    #pragma unroll
    for (int id = tid; id < 128 * 32; id += 256) {
        int r = id >> 5;
        int c = (id & 31) * 4;
        if (col0 + c < Nout) {
            float4 v = *(const float4*)(stg + r * 132 + c);
            float4 bv = *(const float4*)(bias + col0 + c);
            v.x += bv.x; v.y += bv.y; v.z += bv.z; v.w += bv.w;
            *(float4*)(C + (size_t)(m0 + r) * Nout + col0 + c) = v;
        }
    }
}

// ---------------- CSR build ----------------
__global__ void count_kernel(const int* __restrict__ dst, int* __restrict__ deg, int E) {
    int e = blockIdx.x * blockDim.x + threadIdx.x;
    if (e < E) atomicAdd(&deg[dst[e]], 1);
}

__global__ void scan_kernel(const int* __restrict__ deg, int* __restrict__ off, int n) {
    __shared__ int wsum[32];
    int tid = threadIdx.x, lane = tid & 31, wid = tid >> 5;
    int carry = 0;
    for (int base = 0; base < n; base += 1024) {
        int i = base + tid;
        int v = (i < n) ? deg[i] : 0;
        int x = v;
        #pragma unroll
        for (int o = 1; o < 32; o <<= 1) {
            int t = __shfl_up_sync(0xFFFFFFFFu, x, o);
            if (lane >= o) x += t;
        }
        if (lane == 31) wsum[wid] = x;
        __syncthreads();
        if (wid == 0) {
            int y = wsum[lane];
            #pragma unroll
            for (int o = 1; o < 32; o <<= 1) {
                int t = __shfl_up_sync(0xFFFFFFFFu, y, o);
                if (lane >= o) y += t;
            }
            wsum[lane] = y;
        }
        __syncthreads();
        int pre = (wid > 0) ? wsum[wid - 1] : 0;
        if (i < n) off[i] = carry + pre + x - v;
        int total = wsum[31];
        __syncthreads();
        carry += total;
    }
    if (tid == 0) off[n] = carry;
}

__global__ void scatter_kernel(const int* __restrict__ dst, int* __restrict__ cur,
                               int* __restrict__ eid, int E) {
    int e = blockIdx.x * blockDim.x + threadIdx.x;
    if (e < E) {
        int p = atomicAdd(&cur[dst[e]], 1);
        eid[p] = e;
    }
}

// ---------------- fused GATv2 edge pass (layer 1): warp per (dst, head) ----------------
// pass1: logits (xr/att register-cached) + segment max
// pass2: deterministic logit recompute + exp + weighted accumulate
// epilogue: /den + bias + optional self + ELU (concat-head layout)
template <int C>
__global__ void gat_fused1(const int* __restrict__ off, const int* __restrict__ eid,
                           const int* __restrict__ srcv,
                           const float* __restrict__ xl, const float* __restrict__ xr,
                           const float* __restrict__ att, const float* __restrict__ bias,
                           const float* __restrict__ self, float* __restrict__ out, int Nd) {
    int w = (blockIdx.x * blockDim.x + threadIdx.x) >> 5;
    int lane = threadIdx.x & 31;
    if (w >= Nd * H) return;
    int d = w >> 2, h = w & 3;
    constexpr int V = C / 32;

    float attv[V], xrv[V];
    {
        const float* pa = att + h * C + lane * V;
        const float* pr = xr + ((size_t)d * H + h) * C + lane * V;
        #pragma unroll
        for (int v = 0; v < V; v++) { attv[v] = pa[v]; xrv[v] = pr[v]; }
    }
    int b0 = off[d], b1 = off[d + 1];

    float m = -1e30f;
    for (int i = b0; i < b1; i++) {
        int s = srcv[eid[i]];
        const float* p = xl + ((size_t)s * H + h) * C + lane * V;
        float pp = 0.f;
        #pragma unroll
        for (int v = 0; v < V; v++) {
            float g = p[v] + xrv[v];
            g = g > 0.f ? g : 0.2f * g;
            pp = fmaf(g, attv[v], pp);
        }
        #pragma unroll
        for (int o = 16; o; o >>= 1) pp += __shfl_xor_sync(0xFFFFFFFFu, pp, o);
        m = fmaxf(m, pp);
    }

    float den = 0.f, acc[V] = {};
    for (int i = b0; i < b1; i++) {
        int s = srcv[eid[i]];
        const float* p = xl + ((size_t)s * H + h) * C + lane * V;
        float t[V];
        float pp = 0.f;
        #pragma unroll
        for (int v = 0; v < V; v++) {
            t[v] = p[v];
            float g = t[v] + xrv[v];
            g = g > 0.f ? g : 0.2f * g;
            pp = fmaf(g, attv[v], pp);
        }
        #pragma unroll
        for (int o = 16; o; o >>= 1) pp += __shfl_xor_sync(0xFFFFFFFFu, pp, o);
        float a = __expf(pp - m);
        den += a;
        #pragma unroll
        for (int v = 0; v < V; v++) acc[v] = fmaf(a, t[v], acc[v]);
    }

    float inv = 1.f / (den + 1e-16f);
    float* po = out + ((size_t)d * H + h) * C + lane * V;
    #pragma unroll
    for (int v = 0; v < V; v++) {
        float x = acc[v] * inv + bias[h * C + lane * V + v];
        if (self) x += self[(size_t)d * C + lane * V + v];
        po[v] = x > 0.f ? x : (__expf(x) - 1.f);
    }
}

// ---------------- fused GATv2 layer 3: block per dst, warp per head, head-mean fused ----------------
__global__ void gat_fused3(const int* __restrict__ off, const int* __restrict__ eid,
                           const int* __restrict__ srcv,
                           const float* __restrict__ xl, const float* __restrict__ xr,
                           const float* __restrict__ att, const float* __restrict__ bias3,
                           const float* __restrict__ sl3, float* __restrict__ out) {
    __shared__ float sh[H][C3];
    int d = blockIdx.x;
    int h = threadIdx.x >> 5;
    int lane = threadIdx.x & 31;
    constexpr int V = C3 / 32;   // 4

    float attv[V], xrv[V];
    {
        const float* pa = att + h * C3 + lane * V;
        const float* pr = xr + ((size_t)d * H + h) * C3 + lane * V;
        #pragma unroll
        for (int v = 0; v < V; v++) { attv[v] = pa[v]; xrv[v] = pr[v]; }
    }
    int b0 = off[d], b1 = off[d + 1];

    float m = -1e30f;
    for (int i = b0; i < b1; i++) {
        int s = srcv[eid[i]];
        const float4 t = *(const float4*)(xl + ((size_t)s * H + h) * C3 + lane * V);
        float g0 = t.x + xrv[0]; g0 = g0 > 0.f ? g0 : 0.2f * g0;
        float g1 = t.y + xrv[1]; g1 = g1 > 0.f ? g1 : 0.2f * g1;
        float g2 = t.z + xrv[2]; g2 = g2 > 0.f ? g2 : 0.2f * g2;
        float g3 = t.w + xrv[3]; g3 = g3 > 0.f ? g3 : 0.2f * g3;
        float pp = g0 * attv[0] + g1 * attv[1] + g2 * attv[2] + g3 * attv[3];
        #pragma unroll
        for (int o = 16; o; o >>= 1) pp += __shfl_xor_sync(0xFFFFFFFFu, pp, o);
        m = fmaxf(m, pp);
    }

    float den = 0.f, acc[V] = {};
    for (int i = b0; i < b1; i++) {
        int s = srcv[eid[i]];
        const float4 t = *(const float4*)(xl + ((size_t)s * H + h) * C3 + lane * V);
        float g0 = t.x + xrv[0]; g0 = g0 > 0.f ? g0 : 0.2f * g0;
        float g1 = t.y + xrv[1]; g1 = g1 > 0.f ? g1 : 0.2f * g1;
        float g2 = t.z + xrv[2]; g2 = g2 > 0.f ? g2 : 0.2f * g2;
        float g3 = t.w + xrv[3]; g3 = g3 > 0.f ? g3 : 0.2f * g3;
        float pp = g0 * attv[0] + g1 * attv[1] + g2 * attv[2] + g3 * attv[3];
        #pragma unroll
        for (int o = 16; o; o >>= 1) pp += __shfl_xor_sync(0xFFFFFFFFu, pp, o);
        float a = __expf(pp - m);
        den += a;
        acc[0] = fmaf(a, t.x, acc[0]);
        acc[1] = fmaf(a, t.y, acc[1]);
        acc[2] = fmaf(a, t.z, acc[2]);
        acc[3] = fmaf(a, t.w, acc[3]);
    }

    float inv = 1.f / (den + 1e-16f);
    #pragma unroll
    for (int v = 0; v < V; v++) sh[h][lane * V + v] = acc[v] * inv;
    __syncthreads();

    int c = threadIdx.x;   // 0..127
    float s4 = 0.25f * (sh[0][c] + sh[1][c] + sh[2][c] + sh[3][c]);
    float x = s4 + bias3[c] + sl3[(size_t)d * C3 + c];
    out[(size_t)d * C3 + c] = x > 0.f ? x : (__expf(x) - 1.f);
}

// ---------------- host launch ----------------
static inline float* sym(const void* s) {
    void* p = nullptr;
    cudaGetSymbolAddress(&p, s);
    return (float*)p;
}
static inline int* symi(const void* s) {
    void* p = nullptr;
    cudaGetSymbolAddress(&p, s);
    return (int*)p;
}

extern "C" void kernel_launch(void* const* d_in, const int* in_sizes, int n_in,
                              void* d_out, int out_size) {
    const float* x_sample = (const float*)d_in[0];
    const float* x_gene   = (const float*)d_in[1];
    const int*   sg_src   = (const int*)d_in[2];
    const int*   sg_dst   = (const int*)d_in[3];
    const int*   gs_src   = (const int*)d_in[4];
    const int*   gs_dst   = (const int*)d_in[5];
    const float* Wl1_sg = (const float*)d_in[6];
    const float* bl1_sg = (const float*)d_in[7];
    const float* Wr1_sg = (const float*)d_in[8];
    const float* br1_sg = (const float*)d_in[9];
    const float* att1_sg  = (const float*)d_in[10];
    const float* bias1_sg = (const float*)d_in[11];
    const float* Wl1_gs = (const float*)d_in[12];
    const float* bl1_gs = (const float*)d_in[13];
    const float* Wr1_gs = (const float*)d_in[14];
    const float* br1_gs = (const float*)d_in[15];
    const float* att1_gs  = (const float*)d_in[16];
    const float* bias1_gs = (const float*)d_in[17];
    const float* Wl3_gs = (const float*)d_in[18];
    const float* bl3_gs = (const float*)d_in[19];
    const float* Wr3_gs = (const float*)d_in[20];
    const float* br3_gs = (const float*)d_in[21];
    const float* att3_gs  = (const float*)d_in[22];
    const float* bias3_gs = (const float*)d_in[23];
    const float* sl1_W = (const float*)d_in[24];
    const float* sl1_b = (const float*)d_in[25];
    const float* sl3_W = (const float*)d_in[26];
    const float* sl3_b = (const float*)d_in[27];
    float* out = (float*)d_out;

    float* xl_sg = sym(g_xl_sg);
    float* xr_sg = sym(g_xr_sg);
    float* xl_gs = sym(g_xl_gs);
    float* xr_gs = sym(g_xr_gs);
    float* x1_gene = sym(g_x1_gene);
    float* x1_sample = sym(g_x1_sample);
    float* sl1 = sym(g_sl1);
    float* xl3 = sym(g_xl3);
    float* xr3 = sym(g_xr3);
    float* sl3 = sym(g_sl3);
    float* w5p = sym(g_w5p);
    int* deg = symi(g_deg);
    int* off_sg = symi(g_off_sg);
    int* cur_sg = symi(g_cur_sg);
    int* eid_sg = symi(g_eid_sg);
    int* off_gs = symi(g_off_gs);
    int* cur_gs = symi(g_cur_gs);
    int* eid_gs = symi(g_eid_gs);

    static bool attr_done = false;
    if (!attr_done) {
        cudaFuncSetAttribute(gemm_wmma, cudaFuncAttributeMaxDynamicSharedMemorySize, GEMM_SMEM);
        attr_done = true;
    }

    dim3 tb(256);
    int eb = (NE + 255) / 256;

    // ----- CSR build -----
    cudaMemsetAsync(deg, 0, NG * sizeof(int));
    count_kernel<<<eb, tb>>>(sg_dst, deg, NE);
    scan_kernel<<<1, 1024>>>(deg, off_sg, NG);
    cudaMemcpyAsync(cur_sg, off_sg, NG * sizeof(int), cudaMemcpyDeviceToDevice);
    scatter_kernel<<<eb, tb>>>(sg_dst, cur_sg, eid_sg, NE);

    cudaMemsetAsync(deg, 0, NS * sizeof(int));
    count_kernel<<<eb, tb>>>(gs_dst, deg, NE);
    scan_kernel<<<1, 1024>>>(deg, off_gs, NS);
    cudaMemcpyAsync(cur_gs, off_gs, NS * sizeof(int), cudaMemcpyDeviceToDevice);
    scatter_kernel<<<eb, tb>>>(gs_dst, cur_gs, eid_gs, NE);

    // ----- sl1_W pad (N=64 -> 128 cols) -----
    pad_w_kernel<<<(DIN * 128 + 255) / 256, tb>>>(sl1_W, w5p, C1);

    const int MB_NS = NS / 128;            // 32
    const int MB_NG = (NG + 127) / 128;    // 157

    // ----- layer 1: sg (sample -> gene) -----
    gemm_wmma<<<dim3(HC1 / 128, MB_NS), GEMM_THREADS, GEMM_SMEM>>>(x_sample, Wl1_sg, HC1, bl1_sg, xl_sg, NS, HC1);
    gemm_wmma<<<dim3(HC1 / 128, MB_NG), GEMM_THREADS, GEMM_SMEM>>>(x_gene, Wr1_sg, HC1, br1_sg, xr_sg, NG, HC1);
    gat_fused1<C1><<<(NG * H + 7) / 8, tb>>>(off_sg, eid_sg, sg_src, xl_sg, xr_sg,
                                             att1_sg, bias1_sg, nullptr, x1_gene, NG);

    // ----- layer 1: gs (gene -> sample) + self loop -----
    gemm_wmma<<<dim3(HC1 / 128, MB_NG), GEMM_THREADS, GEMM_SMEM>>>(x_gene, Wl1_gs, HC1, bl1_gs, xl_gs, NG, HC1);
    gemm_wmma<<<dim3(HC1 / 128, MB_NS), GEMM_THREADS, GEMM_SMEM>>>(x_sample, Wr1_gs, HC1, br1_gs, xr_gs, NS, HC1);
    gemm_wmma<<<dim3(1, MB_NS), GEMM_THREADS, GEMM_SMEM>>>(x_sample, w5p, 128, sl1_b, sl1, NS, C1);
    gat_fused1<C1><<<(NS * H + 7) / 8, tb>>>(off_gs, eid_gs, gs_src, xl_gs, xr_gs,
                                             att1_gs, bias1_gs, sl1, x1_sample, NS);

    // ----- layer 3: gs (gene -> sample), head mean fused -----
    gemm_wmma<<<dim3(HC3 / 128, MB_NG), GEMM_THREADS, GEMM_SMEM>>>(x1_gene, Wl3_gs, HC3, bl3_gs, xl3, NG, HC3);
    gemm_wmma<<<dim3(HC3 / 128, MB_NS), GEMM_THREADS, GEMM_SMEM>>>(x1_sample, Wr3_gs, HC3, br3_gs, xr3, NS, HC3);
    gemm_wmma<<<dim3(1, MB_NS), GEMM_THREADS, GEMM_SMEM>>>(x1_sample, sl3_W, C3, sl3_b, sl3, NS, C3);
    gat_fused3<<<NS, 128>>>(off_gs, eid_gs, gs_src, xl3, xr3, att3_gs, bias3_gs, sl3, out);
}

// round 6
// speedup vs baseline: 1.4186x; 1.3459x over previous
#include <cuda_runtime.h>
#include <mma.h>
#include <math.h>
#include <stddef.h>
#include <stdint.h>

using namespace nvcuda;

// Round 6 = Round 4 kernel, static-guard removed (harness contract: no static
// guards). Rounds 4/5 were container failures; kernel never executed.

// ---------------- problem constants ----------------
#define NS   4096
#define NG   20000
#define NGP  20096   // padded to multiple of 128
#define NE   131072
#define DIN  256
#define H    4
#define C1   64
#define C3   128
#define HC1  256
#define HC3  512

// ---------------- device scratch (static, no runtime alloc) ----------------
__device__ __align__(128) float g_xl_sg[NS * HC1];
__device__ __align__(128) float g_xr_sg[NGP * HC1];
__device__ __align__(128) float g_xl_gs[NGP * HC1];
__device__ __align__(128) float g_xr_gs[NS * HC1];
__device__ __align__(128) float g_x1_gene[NG * HC1];
__device__ __align__(128) float g_x1_sample[NS * HC1];
__device__ __align__(128) float g_sl1[NS * C1];
__device__ __align__(128) float g_xl3[NGP * HC3];
__device__ __align__(128) float g_xr3[NS * HC3];
__device__ __align__(128) float g_sl3[NS * C3];
__device__ __align__(128) float g_w5p[DIN * 128];   // sl1_W padded to 128 cols

__device__ int g_deg[NG];
__device__ int g_off_sg[NG + 1];
__device__ int g_cur_sg[NG];
__device__ int g_eid_sg[NE];
__device__ int g_off_gs[NS + 1];
__device__ int g_cur_gs[NS];
__device__ int g_eid_gs[NE];

// ---------------- helpers ----------------
__device__ __forceinline__ uint32_t smem_u32(const void* p) {
    uint32_t a;
    asm("{ .reg .u64 t; cvta.to.shared.u64 t, %1; cvt.u32.u64 %0, t; }" : "=r"(a) : "l"(p));
    return a;
}
#define CP_ASYNC16(dst, src) \
    asm volatile("cp.async.ca.shared.global [%0], [%1], 16;" :: "r"(dst), "l"(src))
#define CP_COMMIT() asm volatile("cp.async.commit_group;")
#define CP_WAIT(n)  asm volatile("cp.async.wait_group %0;" :: "n"(n))

// ---------------- pad sl1_W [256,64] -> [256,128] (zero-pad cols) ----------------
__global__ void pad_w_kernel(const float* __restrict__ W, float* __restrict__ WP, int N) {
    int i = blockIdx.x * blockDim.x + threadIdx.x;
    if (i < DIN * 128) {
        int k = i >> 7, c = i & 127;
        WP[i] = (c < N) ? W[k * N + c] : 0.f;
    }
}

// ---------------- WMMA tf32 GEMM: C[M,Nout] = A[M,256] @ B[256,ldB] + bias ----------------
// 256 threads, 8 warps (4 m x 2 n), block tile 128x128, BK=32.
// BOTH A and B double-buffered in smem via cp.async; fragments from smem only.
// C rows stored unguarded: all C buffers padded to gridDim.y*128 rows.
#define GEMM_THREADS 256
// A: 2*128*40 fl = 40960 B ; B: 2*32*132 fl = 33792 B ; total 74752 B
// epilogue staging 128*132*4 = 67584 B reuses the same region
#define GEMM_SMEM 74752
#define A_PITCH 40
#define B_PITCH 132
#define B_OFF   10240   // float offset of B region

__global__ void __launch_bounds__(GEMM_THREADS) gemm_wmma(
    const float* __restrict__ A, const float* __restrict__ B, int ldB,
    const float* __restrict__ bias, float* __restrict__ C, int M, int Nout) {
    extern __shared__ float sm[];
    constexpr int K = 256;
    const int tid = threadIdx.x;
    const int wid = tid >> 5;
    const int warp_m = wid >> 1;     // 0..3
    const int warp_n = wid & 1;      // 0..1
    const int m0 = blockIdx.y * 128;
    const int col0 = blockIdx.x * 128;

    wmma::fragment<wmma::accumulator, 16, 16, 8, float> cfr[2][4];
    #pragma unroll
    for (int i = 0; i < 2; i++)
        #pragma unroll
        for (int t = 0; t < 4; t++) wmma::fill_fragment(cfr[i][t], 0.f);

    // A tile loader: 128 rows x 32 k into buffer b
    auto loadA = [&](int s, int b) {
        const float* Ab = A + (size_t)m0 * K + s * 32;
        float* dst = sm + b * (128 * A_PITCH);
        #pragma unroll
        for (int i = 0; i < 4; i++) {
            int ch = tid + i * 256;
            int r = ch >> 3, c4 = ch & 7;
            float* dp = dst + r * A_PITCH + c4 * 4;
            if (m0 + r < M) {
                CP_ASYNC16(smem_u32(dp), Ab + (size_t)r * K + c4 * 4);
            } else {
                *(float4*)dp = make_float4(0.f, 0.f, 0.f, 0.f);
            }
        }
    };
    // B tile loader: 32 k-rows x 128 cols into buffer b (coalesced)
    auto loadB = [&](int s, int b) {
        const float* Bb = B + (size_t)(s * 32) * ldB + col0;
        float* dst = sm + B_OFF + b * (32 * B_PITCH);
        #pragma unroll
        for (int i = 0; i < 4; i++) {
            int ch = tid + i * 256;          // 0..1023
            int r = ch >> 5, c4 = ch & 31;   // 32 rows x 32 float4
            CP_ASYNC16(smem_u32(dst + r * B_PITCH + c4 * 4), Bb + (size_t)r * ldB + c4 * 4);
        }
    };

    loadA(0, 0); loadB(0, 0);
    CP_COMMIT();

    #pragma unroll 1
    for (int s = 0; s < 8; s++) {
        int b = s & 1;
        if (s < 7) { loadA(s + 1, b ^ 1); loadB(s + 1, b ^ 1); CP_COMMIT(); }
        if (s < 7) { CP_WAIT(1); } else { CP_WAIT(0); }
        __syncthreads();

        const float* As = sm + b * (128 * A_PITCH) + warp_m * 32 * A_PITCH;
        const float* Bs = sm + B_OFF + b * (32 * B_PITCH);
        #pragma unroll
        for (int kk = 0; kk < 4; kk++) {
            wmma::fragment<wmma::matrix_a, 16, 16, 8, wmma::precision::tf32, wmma::row_major> af[2];
            wmma::load_matrix_sync(af[0], As + kk * 8, A_PITCH);
            wmma::load_matrix_sync(af[1], As + 16 * A_PITCH + kk * 8, A_PITCH);
            #pragma unroll
            for (int i = 0; i < 2; i++)
                #pragma unroll
                for (int e = 0; e < af[i].num_elements; e++)
                    af[i].x[e] = wmma::__float_to_tf32(af[i].x[e]);
            #pragma unroll
            for (int t = 0; t < 4; t++) {
                wmma::fragment<wmma::matrix_b, 16, 16, 8, wmma::precision::tf32, wmma::row_major> bf;
                wmma::load_matrix_sync(bf, Bs + kk * 8 * B_PITCH + warp_n * 64 + t * 16, B_PITCH);
                #pragma unroll
                for (int e = 0; e < bf.num_elements; e++)
                    bf.x[e] = wmma::__float_to_tf32(bf.x[e]);
                wmma::mma_sync(cfr[0][t], af[0], bf, cfr[0][t]);
                wmma::mma_sync(cfr[1][t], af[1], bf, cfr[1][t]);
            }
        }
        __syncthreads();
    }

    // epilogue: stage to smem (pitch 132), then copy out with bias + col guard
    float* stg = sm;
    #pragma unroll
    for (int i = 0; i < 2; i++)
        #pragma unroll
        for (int t = 0; t < 4; t++)
            wmma::store_matrix_sync(stg + (warp_m * 32 + i * 16) * 132 + warp_n * 64 + t * 16,
                                    cfr[i][t], 132, wmma::mem_row_major);
    __syncthreads();

    #pragma unroll
    for (int id = tid; id < 128 * 32; id += 256) {
        int r = id >> 5;
        int c = (id & 31) * 4;
        if (col0 + c < Nout) {
            float4 v = *(const float4*)(stg + r * 132 + c);
            float4 bv = *(const float4*)(bias + col0 + c);
            v.x += bv.x; v.y += bv.y; v.z += bv.z; v.w += bv.w;
            *(float4*)(C + (size_t)(m0 + r) * Nout + col0 + c) = v;
        }
    }
}

// ---------------- CSR build ----------------
__global__ void count_kernel(const int* __restrict__ dst, int* __restrict__ deg, int E) {
    int e = blockIdx.x * blockDim.x + threadIdx.x;
    if (e < E) atomicAdd(&deg[dst[e]], 1);
}

__global__ void scan_kernel(const int* __restrict__ deg, int* __restrict__ off, int n) {
    __shared__ int wsum[32];
    int tid = threadIdx.x, lane = tid & 31, wid = tid >> 5;
    int carry = 0;
    for (int base = 0; base < n; base += 1024) {
        int i = base + tid;
        int v = (i < n) ? deg[i] : 0;
        int x = v;
        #pragma unroll
        for (int o = 1; o < 32; o <<= 1) {
            int t = __shfl_up_sync(0xFFFFFFFFu, x, o);
            if (lane >= o) x += t;
        }
        if (lane == 31) wsum[wid] = x;
        __syncthreads();
        if (wid == 0) {
            int y = wsum[lane];
            #pragma unroll
            for (int o = 1; o < 32; o <<= 1) {
                int t = __shfl_up_sync(0xFFFFFFFFu, y, o);
                if (lane >= o) y += t;
            }
            wsum[lane] = y;
        }
        __syncthreads();
        int pre = (wid > 0) ? wsum[wid - 1] : 0;
        if (i < n) off[i] = carry + pre + x - v;
        int total = wsum[31];
        __syncthreads();
        carry += total;
    }
    if (tid == 0) off[n] = carry;
}

__global__ void scatter_kernel(const int* __restrict__ dst, int* __restrict__ cur,
                               int* __restrict__ eid, int E) {
    int e = blockIdx.x * blockDim.x + threadIdx.x;
    if (e < E) {
        int p = atomicAdd(&cur[dst[e]], 1);
        eid[p] = e;
    }
}

// ---------------- fused GATv2 layer-1 edge pass: warp per (dst, head) ----------------
// ONLINE softmax: single gather pass over xl with running max rescale.
template <int C>
__global__ void gat_fused1(const int* __restrict__ off, const int* __restrict__ eid,
                           const int* __restrict__ srcv,
                           const float* __restrict__ xl, const float* __restrict__ xr,
                           const float* __restrict__ att, const float* __restrict__ bias,
                           const float* __restrict__ self, float* __restrict__ out, int Nd) {
    int w = (blockIdx.x * blockDim.x + threadIdx.x) >> 5;
    int lane = threadIdx.x & 31;
    if (w >= Nd * H) return;
    int d = w >> 2, h = w & 3;
    constexpr int V = C / 32;

    float attv[V], xrv[V];
    {
        const float* pa = att + h * C + lane * V;
        const float* pr = xr + ((size_t)d * H + h) * C + lane * V;
        #pragma unroll
        for (int v = 0; v < V; v++) { attv[v] = pa[v]; xrv[v] = pr[v]; }
    }
    int b0 = off[d], b1 = off[d + 1];

    float m = -1e30f, den = 0.f, acc[V] = {};
    for (int i = b0; i < b1; i++) {
        int s = srcv[eid[i]];
        const float* p = xl + ((size_t)s * H + h) * C + lane * V;
        float t[V];
        float pp = 0.f;
        #pragma unroll
        for (int v = 0; v < V; v++) {
            t[v] = p[v];
            float g = t[v] + xrv[v];
            g = g > 0.f ? g : 0.2f * g;
            pp = fmaf(g, attv[v], pp);
        }
        #pragma unroll
        for (int o = 16; o; o >>= 1) pp += __shfl_xor_sync(0xFFFFFFFFu, pp, o);
        float mn = fmaxf(m, pp);
        float sc = __expf(m - mn);
        float a  = __expf(pp - mn);
        den = den * sc + a;
        #pragma unroll
        for (int v = 0; v < V; v++) acc[v] = fmaf(acc[v], sc, a * t[v]);
        m = mn;
    }

    float inv = 1.f / (den + 1e-16f);
    float* po = out + ((size_t)d * H + h) * C + lane * V;
    #pragma unroll
    for (int v = 0; v < V; v++) {
        float x = acc[v] * inv + bias[h * C + lane * V + v];
        if (self) x += self[(size_t)d * C + lane * V + v];
        po[v] = x > 0.f ? x : (__expf(x) - 1.f);
    }
}

// ---------------- fused GATv2 layer 3: block per dst, warp per head, head-mean fused ----------------
__global__ void gat_fused3(const int* __restrict__ off, const int* __restrict__ eid,
                           const int* __restrict__ srcv,
                           const float* __restrict__ xl, const float* __restrict__ xr,
                           const float* __restrict__ att, const float* __restrict__ bias3,
                           const float* __restrict__ sl3, float* __restrict__ out) {
    __shared__ float sh[H][C3];
    int d = blockIdx.x;
    int h = threadIdx.x >> 5;
    int lane = threadIdx.x & 31;
    constexpr int V = C3 / 32;   // 4

    float attv[V], xrv[V];
    {
        const float* pa = att + h * C3 + lane * V;
        const float* pr = xr + ((size_t)d * H + h) * C3 + lane * V;
        #pragma unroll
        for (int v = 0; v < V; v++) { attv[v] = pa[v]; xrv[v] = pr[v]; }
    }
    int b0 = off[d], b1 = off[d + 1];

    float m = -1e30f, den = 0.f, acc[V] = {};
    for (int i = b0; i < b1; i++) {
        int s = srcv[eid[i]];
        const float4 t = *(const float4*)(xl + ((size_t)s * H + h) * C3 + lane * V);
        float g0 = t.x + xrv[0]; g0 = g0 > 0.f ? g0 : 0.2f * g0;
        float g1 = t.y + xrv[1]; g1 = g1 > 0.f ? g1 : 0.2f * g1;
        float g2 = t.z + xrv[2]; g2 = g2 > 0.f ? g2 : 0.2f * g2;
        float g3 = t.w + xrv[3]; g3 = g3 > 0.f ? g3 : 0.2f * g3;
        float pp = g0 * attv[0] + g1 * attv[1] + g2 * attv[2] + g3 * attv[3];
        #pragma unroll
        for (int o = 16; o; o >>= 1) pp += __shfl_xor_sync(0xFFFFFFFFu, pp, o);
        float mn = fmaxf(m, pp);
        float sc = __expf(m - mn);
        float a  = __expf(pp - mn);
        den = den * sc + a;
        acc[0] = fmaf(acc[0], sc, a * t.x);
        acc[1] = fmaf(acc[1], sc, a * t.y);
        acc[2] = fmaf(acc[2], sc, a * t.z);
        acc[3] = fmaf(acc[3], sc, a * t.w);
        m = mn;
    }

    float inv = 1.f / (den + 1e-16f);
    #pragma unroll
    for (int v = 0; v < V; v++) sh[h][lane * V + v] = acc[v] * inv;
    __syncthreads();

    int c = threadIdx.x;   // 0..127
    float s4 = 0.25f * (sh[0][c] + sh[1][c] + sh[2][c] + sh[3][c]);
    float x = s4 + bias3[c] + sl3[(size_t)d * C3 + c];
    out[(size_t)d * C3 + c] = x > 0.f ? x : (__expf(x) - 1.f);
}

// ---------------- host launch ----------------
static inline float* sym(const void* s) {
    void* p = nullptr;
    cudaGetSymbolAddress(&p, s);
    return (float*)p;
}
static inline int* symi(const void* s) {
    void* p = nullptr;
    cudaGetSymbolAddress(&p, s);
    return (int*)p;
}

extern "C" void kernel_launch(void* const* d_in, const int* in_sizes, int n_in,
                              void* d_out, int out_size) {
    const float* x_sample = (const float*)d_in[0];
    const float* x_gene   = (const float*)d_in[1];
    const int*   sg_src   = (const int*)d_in[2];
    const int*   sg_dst   = (const int*)d_in[3];
    const int*   gs_src   = (const int*)d_in[4];
    const int*   gs_dst   = (const int*)d_in[5];
    const float* Wl1_sg = (const float*)d_in[6];
    const float* bl1_sg = (const float*)d_in[7];
    const float* Wr1_sg = (const float*)d_in[8];
    const float* br1_sg = (const float*)d_in[9];
    const float* att1_sg  = (const float*)d_in[10];
    const float* bias1_sg = (const float*)d_in[11];
    const float* Wl1_gs = (const float*)d_in[12];
    const float* bl1_gs = (const float*)d_in[13];
    const float* Wr1_gs = (const float*)d_in[14];
    const float* br1_gs = (const float*)d_in[15];
    const float* att1_gs  = (const float*)d_in[16];
    const float* bias1_gs = (const float*)d_in[17];
    const float* Wl3_gs = (const float*)d_in[18];
    const float* bl3_gs = (const float*)d_in[19];
    const float* Wr3_gs = (const float*)d_in[20];
    const float* br3_gs = (const float*)d_in[21];
    const float* att3_gs  = (const float*)d_in[22];
    const float* bias3_gs = (const float*)d_in[23];
    const float* sl1_W = (const float*)d_in[24];
    const float* sl1_b = (const float*)d_in[25];
    const float* sl3_W = (const float*)d_in[26];
    const float* sl3_b = (const float*)d_in[27];
    float* out = (float*)d_out;

    float* xl_sg = sym(g_xl_sg);
    float* xr_sg = sym(g_xr_sg);
    float* xl_gs = sym(g_xl_gs);
    float* xr_gs = sym(g_xr_gs);
    float* x1_gene = sym(g_x1_gene);
    float* x1_sample = sym(g_x1_sample);
    float* sl1 = sym(g_sl1);
    float* xl3 = sym(g_xl3);
    float* xr3 = sym(g_xr3);
    float* sl3 = sym(g_sl3);
    float* w5p = sym(g_w5p);
    int* deg = symi(g_deg);
    int* off_sg = symi(g_off_sg);
    int* cur_sg = symi(g_cur_sg);
    int* eid_sg = symi(g_eid_sg);
    int* off_gs = symi(g_off_gs);
    int* cur_gs = symi(g_cur_gs);
    int* eid_gs = symi(g_eid_gs);

    cudaFuncSetAttribute(gemm_wmma, cudaFuncAttributeMaxDynamicSharedMemorySize, GEMM_SMEM);

    dim3 tb(256);
    int eb = (NE + 255) / 256;

    // ----- CSR build -----
    cudaMemsetAsync(deg, 0, NG * sizeof(int));
    count_kernel<<<eb, tb>>>(sg_dst, deg, NE);
    scan_kernel<<<1, 1024>>>(deg, off_sg, NG);
    cudaMemcpyAsync(cur_sg, off_sg, NG * sizeof(int), cudaMemcpyDeviceToDevice);
    scatter_kernel<<<eb, tb>>>(sg_dst, cur_sg, eid_sg, NE);

    cudaMemsetAsync(deg, 0, NS * sizeof(int));
    count_kernel<<<eb, tb>>>(gs_dst, deg, NE);
    scan_kernel<<<1, 1024>>>(deg, off_gs, NS);
    cudaMemcpyAsync(cur_gs, off_gs, NS * sizeof(int), cudaMemcpyDeviceToDevice);
    scatter_kernel<<<eb, tb>>>(gs_dst, cur_gs, eid_gs, NE);

    // ----- sl1_W pad (N=64 -> 128 cols) -----
    pad_w_kernel<<<(DIN * 128 + 255) / 256, tb>>>(sl1_W, w5p, C1);

    const int MB_NS = NS / 128;            // 32
    const int MB_NG = (NG + 127) / 128;    // 157

    // ----- layer 1: sg (sample -> gene) -----
    gemm_wmma<<<dim3(HC1 / 128, MB_NS), GEMM_THREADS, GEMM_SMEM>>>(x_sample, Wl1_sg, HC1, bl1_sg, xl_sg, NS, HC1);
    gemm_wmma<<<dim3(HC1 / 128, MB_NG), GEMM_THREADS, GEMM_SMEM>>>(x_gene, Wr1_sg, HC1, br1_sg, xr_sg, NG, HC1);
    gat_fused1<C1><<<(NG * H + 7) / 8, tb>>>(off_sg, eid_sg, sg_src, xl_sg, xr_sg,
                                             att1_sg, bias1_sg, nullptr, x1_gene, NG);

    // ----- layer 1: gs (gene -> sample) + self loop -----
    gemm_wmma<<<dim3(HC1 / 128, MB_NG), GEMM_THREADS, GEMM_SMEM>>>(x_gene, Wl1_gs, HC1, bl1_gs, xl_gs, NG, HC1);
    gemm_wmma<<<dim3(HC1 / 128, MB_NS), GEMM_THREADS, GEMM_SMEM>>>(x_sample, Wr1_gs, HC1, br1_gs, xr_gs, NS, HC1);
    gemm_wmma<<<dim3(1, MB_NS), GEMM_THREADS, GEMM_SMEM>>>(x_sample, w5p, 128, sl1_b, sl1, NS, C1);
    gat_fused1<C1><<<(NS * H + 7) / 8, tb>>>(off_gs, eid_gs, gs_src, xl_gs, xr_gs,
                                             att1_gs, bias1_gs, sl1, x1_sample, NS);

    // ----- layer 3: gs (gene -> sample), head mean fused -----
    gemm_wmma<<<dim3(HC3 / 128, MB_NG), GEMM_THREADS, GEMM_SMEM>>>(x1_gene, Wl3_gs, HC3, bl3_gs, xl3, NG, HC3);
    gemm_wmma<<<dim3(HC3 / 128, MB_NS), GEMM_THREADS, GEMM_SMEM>>>(x1_sample, Wr3_gs, HC3, br3_gs, xr3, NS, HC3);
    gemm_wmma<<<dim3(1, MB_NS), GEMM_THREADS, GEMM_SMEM>>>(x1_sample, sl3_W, C3, sl3_b, sl3, NS, C3);
    gat_fused3<<<NS, 128>>>(off_gs, eid_gs, gs_src, xl3, xr3, att3_gs, bias3_gs, sl3, out);
}

// round 7
// speedup vs baseline: 1.5371x; 1.0835x over previous
#include <cuda_runtime.h>
#include <mma.h>
#include <math.h>
#include <stddef.h>
#include <stdint.h>

using namespace nvcuda;

// ---------------- problem constants ----------------
#define NS   4096
#define NG   20000
#define NGP  20096   // padded to multiple of 128
#define NE   131072
#define DIN  256
#define H    4
#define C1   64
#define C3   128
#define HC1  256
#define HC3  512

// ---------------- device scratch (static, no runtime alloc) ----------------
__device__ __align__(128) float g_xl_sg[NS * HC1];
__device__ __align__(128) float g_xr_sg[NGP * HC1];
__device__ __align__(128) float g_xl_gs[NGP * HC1];
__device__ __align__(128) float g_xr_gs[NS * HC1];
__device__ __align__(128) float g_x1_gene[NG * HC1];
__device__ __align__(128) float g_x1_sample[NS * HC1];
__device__ __align__(128) float g_sl1[NS * C1];
__device__ __align__(128) float g_xl3[NGP * HC3];
__device__ __align__(128) float g_xr3[NS * HC3];
__device__ __align__(128) float g_sl3[NS * C3];
__device__ __align__(128) float g_w5p[DIN * 128];   // sl1_W padded to 128 cols

__device__ int g_deg_sg[NG];
__device__ int g_deg_gs[NS];
__device__ int g_off_sg[NG + 1];
__device__ int g_cur_sg[NG];
__device__ int g_srcs_sg[NE];   // src VALUES grouped by dst
__device__ int g_off_gs[NS + 1];
__device__ int g_cur_gs[NS];
__device__ int g_srcs_gs[NE];

// ---------------- helpers ----------------
__device__ __forceinline__ uint32_t smem_u32(const void* p) {
    uint32_t a;
    asm("{ .reg .u64 t; cvta.to.shared.u64 t, %1; cvt.u32.u64 %0, t; }" : "=r"(a) : "l"(p));
    return a;
}
#define CP_ASYNC16(dst, src) \
    asm volatile("cp.async.ca.shared.global [%0], [%1], 16;" :: "r"(dst), "l"(src))
#define CP_COMMIT() asm volatile("cp.async.commit_group;")
#define CP_WAIT(n)  asm volatile("cp.async.wait_group %0;" :: "n"(n))

// ---------------- pad sl1_W [256,64] -> [256,128] ----------------
__global__ void pad_w_kernel(const float* __restrict__ W, float* __restrict__ WP, int N) {
    int i = blockIdx.x * blockDim.x + threadIdx.x;
    if (i < DIN * 128) {
        int k = i >> 7, c = i & 127;
        WP[i] = (c < N) ? W[k * N + c] : 0.f;
    }
}

// ---------------- WMMA tf32 GEMM (unchanged from R6) ----------------
#define GEMM_THREADS 256
#define GEMM_SMEM 74752
#define A_PITCH 40
#define B_PITCH 132
#define B_OFF   10240

__global__ void __launch_bounds__(GEMM_THREADS) gemm_wmma(
    const float* __restrict__ A, const float* __restrict__ B, int ldB,
    const float* __restrict__ bias, float* __restrict__ C, int M, int Nout) {
    extern __shared__ float sm[];
    constexpr int K = 256;
    const int tid = threadIdx.x;
    const int wid = tid >> 5;
    const int warp_m = wid >> 1;
    const int warp_n = wid & 1;
    const int m0 = blockIdx.y * 128;
    const int col0 = blockIdx.x * 128;

    wmma::fragment<wmma::accumulator, 16, 16, 8, float> cfr[2][4];
    #pragma unroll
    for (int i = 0; i < 2; i++)
        #pragma unroll
        for (int t = 0; t < 4; t++) wmma::fill_fragment(cfr[i][t], 0.f);

    auto loadA = [&](int s, int b) {
        const float* Ab = A + (size_t)m0 * K + s * 32;
        float* dst = sm + b * (128 * A_PITCH);
        #pragma unroll
        for (int i = 0; i < 4; i++) {
            int ch = tid + i * 256;
            int r = ch >> 3, c4 = ch & 7;
            float* dp = dst + r * A_PITCH + c4 * 4;
            if (m0 + r < M) {
                CP_ASYNC16(smem_u32(dp), Ab + (size_t)r * K + c4 * 4);
            } else {
                *(float4*)dp = make_float4(0.f, 0.f, 0.f, 0.f);
            }
        }
    };
    auto loadB = [&](int s, int b) {
        const float* Bb = B + (size_t)(s * 32) * ldB + col0;
        float* dst = sm + B_OFF + b * (32 * B_PITCH);
        #pragma unroll
        for (int i = 0; i < 4; i++) {
            int ch = tid + i * 256;
            int r = ch >> 5, c4 = ch & 31;
            CP_ASYNC16(smem_u32(dst + r * B_PITCH + c4 * 4), Bb + (size_t)r * ldB + c4 * 4);
        }
    };

    loadA(0, 0); loadB(0, 0);
    CP_COMMIT();

    #pragma unroll 1
    for (int s = 0; s < 8; s++) {
        int b = s & 1;
        if (s < 7) { loadA(s + 1, b ^ 1); loadB(s + 1, b ^ 1); CP_COMMIT(); }
        if (s < 7) { CP_WAIT(1); } else { CP_WAIT(0); }
        __syncthreads();

        const float* As = sm + b * (128 * A_PITCH) + warp_m * 32 * A_PITCH;
        const float* Bs = sm + B_OFF + b * (32 * B_PITCH);
        #pragma unroll
        for (int kk = 0; kk < 4; kk++) {
            wmma::fragment<wmma::matrix_a, 16, 16, 8, wmma::precision::tf32, wmma::row_major> af[2];
            wmma::load_matrix_sync(af[0], As + kk * 8, A_PITCH);
            wmma::load_matrix_sync(af[1], As + 16 * A_PITCH + kk * 8, A_PITCH);
            #pragma unroll
            for (int i = 0; i < 2; i++)
                #pragma unroll
                for (int e = 0; e < af[i].num_elements; e++)
                    af[i].x[e] = wmma::__float_to_tf32(af[i].x[e]);
            #pragma unroll
            for (int t = 0; t < 4; t++) {
                wmma::fragment<wmma::matrix_b, 16, 16, 8, wmma::precision::tf32, wmma::row_major> bf;
                wmma::load_matrix_sync(bf, Bs + kk * 8 * B_PITCH + warp_n * 64 + t * 16, B_PITCH);
                #pragma unroll
                for (int e = 0; e < bf.num_elements; e++)
                    bf.x[e] = wmma::__float_to_tf32(bf.x[e]);
                wmma::mma_sync(cfr[0][t], af[0], bf, cfr[0][t]);
                wmma::mma_sync(cfr[1][t], af[1], bf, cfr[1][t]);
            }
        }
        __syncthreads();
    }

    float* stg = sm;
    #pragma unroll
    for (int i = 0; i < 2; i++)
        #pragma unroll
        for (int t = 0; t < 4; t++)
            wmma::store_matrix_sync(stg + (warp_m * 32 + i * 16) * 132 + warp_n * 64 + t * 16,
                                    cfr[i][t], 132, wmma::mem_row_major);
    __syncthreads();

    #pragma unroll
    for (int id = tid; id < 128 * 32; id += 256) {
        int r = id >> 5;
        int c = (id & 31) * 4;
        if (col0 + c < Nout) {
            float4 v = *(const float4*)(stg + r * 132 + c);
            float4 bv = *(const float4*)(bias + col0 + c);
            v.x += bv.x; v.y += bv.y; v.z += bv.z; v.w += bv.w;
            *(float4*)(C + (size_t)(m0 + r) * Nout + col0 + c) = v;
        }
    }
}

// ---------------- CSR build: fused dual-relation kernels ----------------
__global__ void zero2_kernel(int* __restrict__ dsg, int* __restrict__ dgs) {
    int i = blockIdx.x * blockDim.x + threadIdx.x;
    if (i < NG) dsg[i] = 0;
    if (i < NS) dgs[i] = 0;
}

__global__ void count2_kernel(const int* __restrict__ sg_dst, const int* __restrict__ gs_dst,
                              int* __restrict__ dsg, int* __restrict__ dgs) {
    int e = blockIdx.x * blockDim.x + threadIdx.x;
    if (e < NE) {
        atomicAdd(&dsg[sg_dst[e]], 1);
        atomicAdd(&dgs[gs_dst[e]], 1);
    }
}

// grid=2: block 0 scans sg (n=NG), block 1 scans gs (n=NS); writes off AND cur.
__global__ void scan2_kernel(const int* __restrict__ dsg, int* __restrict__ off_sg, int* __restrict__ cur_sg,
                             const int* __restrict__ dgs, int* __restrict__ off_gs, int* __restrict__ cur_gs) {
    const int* deg = (blockIdx.x == 0) ? dsg : dgs;
    int* off = (blockIdx.x == 0) ? off_sg : off_gs;
    int* cur = (blockIdx.x == 0) ? cur_sg : cur_gs;
    int n = (blockIdx.x == 0) ? NG : NS;
    __shared__ int wsum[32];
    int tid = threadIdx.x, lane = tid & 31, wid = tid >> 5;
    int carry = 0;
    for (int base = 0; base < n; base += 1024) {
        int i = base + tid;
        int v = (i < n) ? deg[i] : 0;
        int x = v;
        #pragma unroll
        for (int o = 1; o < 32; o <<= 1) {
            int t = __shfl_up_sync(0xFFFFFFFFu, x, o);
            if (lane >= o) x += t;
        }
        if (lane == 31) wsum[wid] = x;
        __syncthreads();
        if (wid == 0) {
            int y = wsum[lane];
            #pragma unroll
            for (int o = 1; o < 32; o <<= 1) {
                int t = __shfl_up_sync(0xFFFFFFFFu, y, o);
                if (lane >= o) y += t;
            }
            wsum[lane] = y;
        }
        __syncthreads();
        int pre = (wid > 0) ? wsum[wid - 1] : 0;
        if (i < n) {
            int e = carry + pre + x - v;
            off[i] = e;
            cur[i] = e;
        }
        int total = wsum[31];
        __syncthreads();
        carry += total;
    }
    if (tid == 0) off[n] = carry;
}

// scatter SRC VALUES (not edge ids) grouped by dst, both relations
__global__ void scatter2_kernel(const int* __restrict__ sg_src, const int* __restrict__ sg_dst,
                                int* __restrict__ cur_sg, int* __restrict__ srcs_sg,
                                const int* __restrict__ gs_src, const int* __restrict__ gs_dst,
                                int* __restrict__ cur_gs, int* __restrict__ srcs_gs) {
    int e = blockIdx.x * blockDim.x + threadIdx.x;
    if (e < NE) {
        int p = atomicAdd(&cur_sg[sg_dst[e]], 1);
        srcs_sg[p] = sg_src[e];
        int q = atomicAdd(&cur_gs[gs_dst[e]], 1);
        srcs_gs[q] = gs_src[e];
    }
}

// ---------------- layer-1 GAT edge pass: ONE WARP per dst, all 4 heads ----------------
// Lane l holds floats [l*8, l*8+8) of the 256-float (H*C1) row: head = l>>3,
// channel-in-head = (l&7)*8+v. Per-head online softmax in 8-lane groups.
__global__ void gat1_warp(const int* __restrict__ off, const int* __restrict__ srcs,
                          const float* __restrict__ xl, const float* __restrict__ xr,
                          const float* __restrict__ att, const float* __restrict__ bias,
                          const float* __restrict__ self, float* __restrict__ out, int Nd) {
    int d = (blockIdx.x * blockDim.x + threadIdx.x) >> 5;
    int lane = threadIdx.x & 31;
    if (d >= Nd) return;

    float attv[8], xrv[8];
    {
        const float4* pa = (const float4*)(att + lane * 8);
        const float4* pr = (const float4*)(xr + (size_t)d * HC1 + lane * 8);
        float4 a0 = pa[0], a1 = pa[1], r0 = pr[0], r1 = pr[1];
        attv[0]=a0.x; attv[1]=a0.y; attv[2]=a0.z; attv[3]=a0.w;
        attv[4]=a1.x; attv[5]=a1.y; attv[6]=a1.z; attv[7]=a1.w;
        xrv[0]=r0.x; xrv[1]=r0.y; xrv[2]=r0.z; xrv[3]=r0.w;
        xrv[4]=r1.x; xrv[5]=r1.y; xrv[6]=r1.z; xrv[7]=r1.w;
    }
    int b0 = off[d], b1 = off[d + 1];

    float m = -1e30f, den = 0.f, acc[8] = {};
    int s = (b0 < b1) ? srcs[b0] : 0;
    for (int i = b0; i < b1; i++) {
        int s_next = (i + 1 < b1) ? srcs[i + 1] : 0;
        const float4* p = (const float4*)(xl + (size_t)s * HC1 + lane * 8);
        float4 t0 = p[0], t1 = p[1];
        float t[8] = {t0.x, t0.y, t0.z, t0.w, t1.x, t1.y, t1.z, t1.w};
        float pp = 0.f;
        #pragma unroll
        for (int v = 0; v < 8; v++) {
            float g = t[v] + xrv[v];
            g = g > 0.f ? g : 0.2f * g;
            pp = fmaf(g, attv[v], pp);
        }
        // reduce within 8-lane head group
        pp += __shfl_xor_sync(0xFFFFFFFFu, pp, 1);
        pp += __shfl_xor_sync(0xFFFFFFFFu, pp, 2);
        pp += __shfl_xor_sync(0xFFFFFFFFu, pp, 4);
        float mn = fmaxf(m, pp);
        float sc = __expf(m - mn);
        float a  = __expf(pp - mn);
        den = den * sc + a;
        #pragma unroll
        for (int v = 0; v < 8; v++) acc[v] = fmaf(acc[v], sc, a * t[v]);
        m = mn;
        s = s_next;
    }

    float inv = 1.f / (den + 1e-16f);
    float ov[8];
    #pragma unroll
    for (int v = 0; v < 8; v++) {
        float x = acc[v] * inv + bias[lane * 8 + v];
        if (self) x += self[(size_t)d * C1 + (lane & 7) * 8 + v];
        ov[v] = x > 0.f ? x : (__expf(x) - 1.f);
    }
    float4* po = (float4*)(out + (size_t)d * HC1 + lane * 8);
    po[0] = make_float4(ov[0], ov[1], ov[2], ov[3]);
    po[1] = make_float4(ov[4], ov[5], ov[6], ov[7]);
}

// ---------------- layer-3 GAT edge pass: ONE WARP per dst, all 4 heads + head mean ----------------
// Lane l holds floats [l*16, l*16+16) of the 512-float (H*C3) row: head = l>>3,
// channel chunk = (l&7)*16. Head-mean via shfl_xor 8,16; lanes 0-7 write output.
__global__ void gat3_warp(const int* __restrict__ off, const int* __restrict__ srcs,
                          const float* __restrict__ xl, const float* __restrict__ xr,
                          const float* __restrict__ att, const float* __restrict__ bias3,
                          const float* __restrict__ sl3, float* __restrict__ out) {
    int d = (blockIdx.x * blockDim.x + threadIdx.x) >> 5;
    int lane = threadIdx.x & 31;
    if (d >= NS) return;

    float attv[16], xrv[16];
    {
        const float4* pa = (const float4*)(att + lane * 16);
        const float4* pr = (const float4*)(xr + (size_t)d * HC3 + lane * 16);
        #pragma unroll
        for (int q = 0; q < 4; q++) {
            float4 a = pa[q], r = pr[q];
            attv[q*4+0]=a.x; attv[q*4+1]=a.y; attv[q*4+2]=a.z; attv[q*4+3]=a.w;
            xrv[q*4+0]=r.x; xrv[q*4+1]=r.y; xrv[q*4+2]=r.z; xrv[q*4+3]=r.w;
        }
    }
    int b0 = off[d], b1 = off[d + 1];

    float m = -1e30f, den = 0.f, acc[16] = {};
    int s = (b0 < b1) ? srcs[b0] : 0;
    for (int i = b0; i < b1; i++) {
        int s_next = (i + 1 < b1) ? srcs[i + 1] : 0;
        const float4* p = (const float4*)(xl + (size_t)s * HC3 + lane * 16);
        float t[16];
        #pragma unroll
        for (int q = 0; q < 4; q++) {
            float4 tv = p[q];
            t[q*4+0]=tv.x; t[q*4+1]=tv.y; t[q*4+2]=tv.z; t[q*4+3]=tv.w;
        }
        float pp = 0.f;
        #pragma unroll
        for (int v = 0; v < 16; v++) {
            float g = t[v] + xrv[v];
            g = g > 0.f ? g : 0.2f * g;
            pp = fmaf(g, attv[v], pp);
        }
        pp += __shfl_xor_sync(0xFFFFFFFFu, pp, 1);
        pp += __shfl_xor_sync(0xFFFFFFFFu, pp, 2);
        pp += __shfl_xor_sync(0xFFFFFFFFu, pp, 4);
        float mn = fmaxf(m, pp);
        float sc = __expf(m - mn);
        float a  = __expf(pp - mn);
        den = den * sc + a;
        #pragma unroll
        for (int v = 0; v < 16; v++) acc[v] = fmaf(acc[v], sc, a * t[v]);
        m = mn;
        s = s_next;
    }

    float inv = 1.f / (den + 1e-16f);
    // head mean across lanes {l, l^8, l^16, l^24} (same channel chunk, 4 heads)
    float ov[16];
    #pragma unroll
    for (int v = 0; v < 16; v++) {
        float hv = acc[v] * inv;
        hv += __shfl_xor_sync(0xFFFFFFFFu, hv, 8);
        hv += __shfl_xor_sync(0xFFFFFFFFu, hv, 16);
        ov[v] = 0.25f * hv;
    }
    if (lane < 8) {
        #pragma unroll
        for (int v = 0; v < 16; v++) {
            int c = lane * 16 + v;
            float x = ov[v] + bias3[c] + sl3[(size_t)d * C3 + c];
            ov[v] = x > 0.f ? x : (__expf(x) - 1.f);
        }
        float4* po = (float4*)(out + (size_t)d * C3 + lane * 16);
        #pragma unroll
        for (int q = 0; q < 4; q++)
            po[q] = make_float4(ov[q*4+0], ov[q*4+1], ov[q*4+2], ov[q*4+3]);
    }
}

// ---------------- host launch ----------------
static inline float* sym(const void* s) {
    void* p = nullptr;
    cudaGetSymbolAddress(&p, s);
    return (float*)p;
}
static inline int* symi(const void* s) {
    void* p = nullptr;
    cudaGetSymbolAddress(&p, s);
    return (int*)p;
}

extern "C" void kernel_launch(void* const* d_in, const int* in_sizes, int n_in,
                              void* d_out, int out_size) {
    const float* x_sample = (const float*)d_in[0];
    const float* x_gene   = (const float*)d_in[1];
    const int*   sg_src   = (const int*)d_in[2];
    const int*   sg_dst   = (const int*)d_in[3];
    const int*   gs_src   = (const int*)d_in[4];
    const int*   gs_dst   = (const int*)d_in[5];
    const float* Wl1_sg = (const float*)d_in[6];
    const float* bl1_sg = (const float*)d_in[7];
    const float* Wr1_sg = (const float*)d_in[8];
    const float* br1_sg = (const float*)d_in[9];
    const float* att1_sg  = (const float*)d_in[10];
    const float* bias1_sg = (const float*)d_in[11];
    const float* Wl1_gs = (const float*)d_in[12];
    const float* bl1_gs = (const float*)d_in[13];
    const float* Wr1_gs = (const float*)d_in[14];
    const float* br1_gs = (const float*)d_in[15];
    const float* att1_gs  = (const float*)d_in[16];
    const float* bias1_gs = (const float*)d_in[17];
    const float* Wl3_gs = (const float*)d_in[18];
    const float* bl3_gs = (const float*)d_in[19];
    const float* Wr3_gs = (const float*)d_in[20];
    const float* br3_gs = (const float*)d_in[21];
    const float* att3_gs  = (const float*)d_in[22];
    const float* bias3_gs = (const float*)d_in[23];
    const float* sl1_W = (const float*)d_in[24];
    const float* sl1_b = (const float*)d_in[25];
    const float* sl3_W = (const float*)d_in[26];
    const float* sl3_b = (const float*)d_in[27];
    float* out = (float*)d_out;

    float* xl_sg = sym(g_xl_sg);
    float* xr_sg = sym(g_xr_sg);
    float* xl_gs = sym(g_xl_gs);
    float* xr_gs = sym(g_xr_gs);
    float* x1_gene = sym(g_x1_gene);
    float* x1_sample = sym(g_x1_sample);
    float* sl1 = sym(g_sl1);
    float* xl3 = sym(g_xl3);
    float* xr3 = sym(g_xr3);
    float* sl3 = sym(g_sl3);
    float* w5p = sym(g_w5p);
    int* deg_sg = symi(g_deg_sg);
    int* deg_gs = symi(g_deg_gs);
    int* off_sg = symi(g_off_sg);
    int* cur_sg = symi(g_cur_sg);
    int* srcs_sg = symi(g_srcs_sg);
    int* off_gs = symi(g_off_gs);
    int* cur_gs = symi(g_cur_gs);
    int* srcs_gs = symi(g_srcs_gs);

    cudaFuncSetAttribute(gemm_wmma, cudaFuncAttributeMaxDynamicSharedMemorySize, GEMM_SMEM);

    dim3 tb(256);
    int eb = (NE + 255) / 256;

    // ----- CSR build (fused, both relations) -----
    zero2_kernel<<<(NG + 255) / 256, tb>>>(deg_sg, deg_gs);
    count2_kernel<<<eb, tb>>>(sg_dst, gs_dst, deg_sg, deg_gs);
    scan2_kernel<<<2, 1024>>>(deg_sg, off_sg, cur_sg, deg_gs, off_gs, cur_gs);
    scatter2_kernel<<<eb, tb>>>(sg_src, sg_dst, cur_sg, srcs_sg,
                                gs_src, gs_dst, cur_gs, srcs_gs);

    // ----- sl1_W pad -----
    pad_w_kernel<<<(DIN * 128 + 255) / 256, tb>>>(sl1_W, w5p, C1);

    const int MB_NS = NS / 128;            // 32
    const int MB_NG = (NG + 127) / 128;    // 157

    // ----- layer 1: sg (sample -> gene) -----
    gemm_wmma<<<dim3(HC1 / 128, MB_NS), GEMM_THREADS, GEMM_SMEM>>>(x_sample, Wl1_sg, HC1, bl1_sg, xl_sg, NS, HC1);
    gemm_wmma<<<dim3(HC1 / 128, MB_NG), GEMM_THREADS, GEMM_SMEM>>>(x_gene, Wr1_sg, HC1, br1_sg, xr_sg, NG, HC1);
    gat1_warp<<<(NG * 32 + 255) / 256, tb>>>(off_sg, srcs_sg, xl_sg, xr_sg,
                                             att1_sg, bias1_sg, nullptr, x1_gene, NG);

    // ----- layer 1: gs (gene -> sample) + self loop -----
    gemm_wmma<<<dim3(HC1 / 128, MB_NG), GEMM_THREADS, GEMM_SMEM>>>(x_gene, Wl1_gs, HC1, bl1_gs, xl_gs, NG, HC1);
    gemm_wmma<<<dim3(HC1 / 128, MB_NS), GEMM_THREADS, GEMM_SMEM>>>(x_sample, Wr1_gs, HC1, br1_gs, xr_gs, NS, HC1);
    gemm_wmma<<<dim3(1, MB_NS), GEMM_THREADS, GEMM_SMEM>>>(x_sample, w5p, 128, sl1_b, sl1, NS, C1);
    gat1_warp<<<(NS * 32 + 255) / 256, tb>>>(off_gs, srcs_gs, xl_gs, xr_gs,
                                             att1_gs, bias1_gs, sl1, x1_sample, NS);

    // ----- layer 3: gs (gene -> sample), head mean fused -----
    gemm_wmma<<<dim3(HC3 / 128, MB_NG), GEMM_THREADS, GEMM_SMEM>>>(x1_gene, Wl3_gs, HC3, bl3_gs, xl3, NG, HC3);
    gemm_wmma<<<dim3(HC3 / 128, MB_NS), GEMM_THREADS, GEMM_SMEM>>>(x1_sample, Wr3_gs, HC3, br3_gs, xr3, NS, HC3);
    gemm_wmma<<<dim3(1, MB_NS), GEMM_THREADS, GEMM_SMEM>>>(x1_sample, sl3_W, C3, sl3_b, sl3, NS, C3);
    gat3_warp<<<(NS * 32 + 255) / 256, tb>>>(off_gs, srcs_gs, xl3, xr3, att3_gs, bias3_gs, sl3, out);
}

// round 8
// speedup vs baseline: 1.9455x; 1.2657x over previous
#include <cuda_runtime.h>
#include <mma.h>
#include <math.h>
#include <stddef.h>
#include <stdint.h>

using namespace nvcuda;

// ---------------- problem constants ----------------
#define NS   4096
#define NG   20000
#define NGP  20096   // padded to multiple of 128
#define NE   131072
#define DIN  256
#define H    4
#define C1   64
#define C3   128
#define HC1  256
#define HC3  512

// ---------------- device scratch ----------------
__device__ __align__(128) float g_xl_sg[NS * HC1];
__device__ __align__(128) float g_xr_sg[NGP * HC1];
__device__ __align__(128) float g_xl_gs[NGP * HC1];
__device__ __align__(128) float g_xr_gs[NS * HC1];
__device__ __align__(128) float g_x1_gene[NG * HC1];
__device__ __align__(128) float g_x1_sample[NS * HC1];
__device__ __align__(128) float g_sl1[NS * C1];
__device__ __align__(128) float g_xl3[NGP * HC3];
__device__ __align__(128) float g_xr3[NS * HC3];
__device__ __align__(128) float g_sl3[NS * C3];
__device__ __align__(128) float g_w5p[DIN * 128];   // sl1_W padded to 128 cols
__device__ __align__(128) float g_b5p[128];         // sl1_b padded

__device__ int g_deg_sg[NG];
__device__ int g_deg_gs[NS];
__device__ int g_off_sg[NG + 1];
__device__ int g_cur_sg[NG];
__device__ int g_srcs_sg[NE];
__device__ int g_off_gs[NS + 1];
__device__ int g_cur_gs[NS];
__device__ int g_srcs_gs[NE];

// ---------------- helpers ----------------
__device__ __forceinline__ uint32_t smem_u32(const void* p) {
    uint32_t a;
    asm("{ .reg .u64 t; cvta.to.shared.u64 t, %1; cvt.u32.u64 %0, t; }" : "=r"(a) : "l"(p));
    return a;
}
#define CP_ASYNC16(dst, src) \
    asm volatile("cp.async.ca.shared.global [%0], [%1], 16;" :: "r"(dst), "l"(src))
#define CP_COMMIT() asm volatile("cp.async.commit_group;")
#define CP_WAIT(n)  asm volatile("cp.async.wait_group %0;" :: "n"(n))

// ---------------- pad sl1_W [256,64] -> [256,128], sl1_b [64] -> [128] ----------------
__global__ void pad_w_kernel(const float* __restrict__ W, const float* __restrict__ b,
                             float* __restrict__ WP, float* __restrict__ bP) {
    int i = blockIdx.x * blockDim.x + threadIdx.x;
    if (i < DIN * 128) {
        int k = i >> 7, c = i & 127;
        WP[i] = (c < C1) ? W[k * C1 + c] : 0.f;
    }
    if (i < 128) bP[i] = (i < C1) ? b[i] : 0.f;
}

// ---------------- batched WMMA tf32 GEMM ----------------
// Each segment: C[M,Nout] = A[M,256] @ B[256,ldB] + bias. Block tile 128x128,
// 8 warps, BK=32, A+B double-buffered via cp.async. C rows unguarded (padded
// buffers); cols guarded by Nout.
struct GemmSeg {
    const float* A; const float* B; const float* bias; float* C;
    int ldB; int M; int Nout; int nx; int blk0;
};
struct GemmBatch { GemmSeg seg[6]; int nseg; };

#define GEMM_THREADS 256
#define A_PITCH 36
#define B_PITCH 132
#define B_OFF   9216        // 2*128*36 floats
#define GEMM_SMEM 70656     // (9216 + 2*32*132) * 4 bytes

__global__ void __launch_bounds__(GEMM_THREADS) gemm_batch(GemmBatch P) {
    extern __shared__ float sm[];
    constexpr int K = 256;
    const int tid = threadIdx.x;
    const int wid = tid >> 5;
    const int warp_m = wid >> 1;
    const int warp_n = wid & 1;

    GemmSeg g = P.seg[0];
    #pragma unroll
    for (int i = 1; i < 6; i++)
        if (i < P.nseg && (int)blockIdx.x >= P.seg[i].blk0) g = P.seg[i];
    int lb = blockIdx.x - g.blk0;
    const int m0 = (lb / g.nx) * 128;
    const int col0 = (lb % g.nx) * 128;

    wmma::fragment<wmma::accumulator, 16, 16, 8, float> cfr[2][4];
    #pragma unroll
    for (int i = 0; i < 2; i++)
        #pragma unroll
        for (int t = 0; t < 4; t++) wmma::fill_fragment(cfr[i][t], 0.f);

    auto loadA = [&](int s, int b) {
        const float* Ab = g.A + (size_t)m0 * K + s * 32;
        float* dst = sm + b * (128 * A_PITCH);
        #pragma unroll
        for (int i = 0; i < 4; i++) {
            int ch = tid + i * 256;
            int r = ch >> 3, c4 = ch & 7;
            float* dp = dst + r * A_PITCH + c4 * 4;
            if (m0 + r < g.M) {
                CP_ASYNC16(smem_u32(dp), Ab + (size_t)r * K + c4 * 4);
            } else {
                *(float4*)dp = make_float4(0.f, 0.f, 0.f, 0.f);
            }
        }
    };
    auto loadB = [&](int s, int b) {
        const float* Bb = g.B + (size_t)(s * 32) * g.ldB + col0;
        float* dst = sm + B_OFF + b * (32 * B_PITCH);
        #pragma unroll
        for (int i = 0; i < 4; i++) {
            int ch = tid + i * 256;
            int r = ch >> 5, c4 = ch & 31;
            CP_ASYNC16(smem_u32(dst + r * B_PITCH + c4 * 4), Bb + (size_t)r * g.ldB + c4 * 4);
        }
    };

    loadA(0, 0); loadB(0, 0);
    CP_COMMIT();

    #pragma unroll 1
    for (int s = 0; s < 8; s++) {
        int b = s & 1;
        if (s < 7) { loadA(s + 1, b ^ 1); loadB(s + 1, b ^ 1); CP_COMMIT(); }
        if (s < 7) { CP_WAIT(1); } else { CP_WAIT(0); }
        __syncthreads();

        const float* As = sm + b * (128 * A_PITCH) + warp_m * 32 * A_PITCH;
        const float* Bs = sm + B_OFF + b * (32 * B_PITCH);
        #pragma unroll
        for (int kk = 0; kk < 4; kk++) {
            wmma::fragment<wmma::matrix_a, 16, 16, 8, wmma::precision::tf32, wmma::row_major> af[2];
            wmma::load_matrix_sync(af[0], As + kk * 8, A_PITCH);
            wmma::load_matrix_sync(af[1], As + 16 * A_PITCH + kk * 8, A_PITCH);
            #pragma unroll
            for (int i = 0; i < 2; i++)
                #pragma unroll
                for (int e = 0; e < af[i].num_elements; e++)
                    af[i].x[e] = wmma::__float_to_tf32(af[i].x[e]);
            #pragma unroll
            for (int t = 0; t < 4; t++) {
                wmma::fragment<wmma::matrix_b, 16, 16, 8, wmma::precision::tf32, wmma::row_major> bf;
                wmma::load_matrix_sync(bf, Bs + kk * 8 * B_PITCH + warp_n * 64 + t * 16, B_PITCH);
                #pragma unroll
                for (int e = 0; e < bf.num_elements; e++)
                    bf.x[e] = wmma::__float_to_tf32(bf.x[e]);
                wmma::mma_sync(cfr[0][t], af[0], bf, cfr[0][t]);
                wmma::mma_sync(cfr[1][t], af[1], bf, cfr[1][t]);
            }
        }
        __syncthreads();
    }

    float* stg = sm;
    #pragma unroll
    for (int i = 0; i < 2; i++)
        #pragma unroll
        for (int t = 0; t < 4; t++)
            wmma::store_matrix_sync(stg + (warp_m * 32 + i * 16) * 132 + warp_n * 64 + t * 16,
                                    cfr[i][t], 132, wmma::mem_row_major);
    __syncthreads();

    #pragma unroll
    for (int id = tid; id < 128 * 32; id += 256) {
        int r = id >> 5;
        int c = (id & 31) * 4;
        if (col0 + c < g.Nout) {
            float4 v = *(const float4*)(stg + r * 132 + c);
            float4 bv = *(const float4*)(g.bias + col0 + c);
            v.x += bv.x; v.y += bv.y; v.z += bv.z; v.w += bv.w;
            *(float4*)(g.C + (size_t)(m0 + r) * g.Nout + col0 + c) = v;
        }
    }
}

// ---------------- CSR build (dual relation) ----------------
__global__ void zero2_kernel(int* __restrict__ dsg, int* __restrict__ dgs) {
    int i = blockIdx.x * blockDim.x + threadIdx.x;
    if (i < NG) dsg[i] = 0;
    if (i < NS) dgs[i] = 0;
}

__global__ void count2_kernel(const int* __restrict__ sg_dst, const int* __restrict__ gs_dst,
                              int* __restrict__ dsg, int* __restrict__ dgs) {
    int e = blockIdx.x * blockDim.x + threadIdx.x;
    if (e < NE) {
        atomicAdd(&dsg[sg_dst[e]], 1);
        atomicAdd(&dgs[gs_dst[e]], 1);
    }
}

__global__ void scan2_kernel(const int* __restrict__ dsg, int* __restrict__ off_sg, int* __restrict__ cur_sg,
                             const int* __restrict__ dgs, int* __restrict__ off_gs, int* __restrict__ cur_gs) {
    const int* deg = (blockIdx.x == 0) ? dsg : dgs;
    int* off = (blockIdx.x == 0) ? off_sg : off_gs;
    int* cur = (blockIdx.x == 0) ? cur_sg : cur_gs;
    int n = (blockIdx.x == 0) ? NG : NS;
    __shared__ int wsum[32];
    int tid = threadIdx.x, lane = tid & 31, wid = tid >> 5;
    int carry = 0;
    for (int base = 0; base < n; base += 1024) {
        int i = base + tid;
        int v = (i < n) ? deg[i] : 0;
        int x = v;
        #pragma unroll
        for (int o = 1; o < 32; o <<= 1) {
            int t = __shfl_up_sync(0xFFFFFFFFu, x, o);
            if (lane >= o) x += t;
        }
        if (lane == 31) wsum[wid] = x;
        __syncthreads();
        if (wid == 0) {
            int y = wsum[lane];
            #pragma unroll
            for (int o = 1; o < 32; o <<= 1) {
                int t = __shfl_up_sync(0xFFFFFFFFu, y, o);
                if (lane >= o) y += t;
            }
            wsum[lane] = y;
        }
        __syncthreads();
        int pre = (wid > 0) ? wsum[wid - 1] : 0;
        if (i < n) {
            int e = carry + pre + x - v;
            off[i] = e;
            cur[i] = e;
        }
        int total = wsum[31];
        __syncthreads();
        carry += total;
    }
    if (tid == 0) off[n] = carry;
}

__global__ void scatter2_kernel(const int* __restrict__ sg_src, const int* __restrict__ sg_dst,
                                int* __restrict__ cur_sg, int* __restrict__ srcs_sg,
                                const int* __restrict__ gs_src, const int* __restrict__ gs_dst,
                                int* __restrict__ cur_gs, int* __restrict__ srcs_gs) {
    int e = blockIdx.x * blockDim.x + threadIdx.x;
    if (e < NE) {
        int p = atomicAdd(&cur_sg[sg_dst[e]], 1);
        srcs_sg[p] = sg_src[e];
        int q = atomicAdd(&cur_gs[gs_dst[e]], 1);
        srcs_gs[q] = gs_src[e];
    }
}

// ---------------- layer-1 GAT core: warp per dst, all 4 heads ----------------
__device__ __forceinline__ void gat1_core(int d, int lane,
                                          const int* __restrict__ off, const int* __restrict__ srcs,
                                          const float* __restrict__ xl, const float* __restrict__ xr,
                                          const float* __restrict__ att, const float* __restrict__ bias,
                                          const float* __restrict__ self, float* __restrict__ out) {
    float attv[8], xrv[8];
    {
        const float4* pa = (const float4*)(att + lane * 8);
        const float4* pr = (const float4*)(xr + (size_t)d * HC1 + lane * 8);
        float4 a0 = pa[0], a1 = pa[1], r0 = pr[0], r1 = pr[1];
        attv[0]=a0.x; attv[1]=a0.y; attv[2]=a0.z; attv[3]=a0.w;
        attv[4]=a1.x; attv[5]=a1.y; attv[6]=a1.z; attv[7]=a1.w;
        xrv[0]=r0.x; xrv[1]=r0.y; xrv[2]=r0.z; xrv[3]=r0.w;
        xrv[4]=r1.x; xrv[5]=r1.y; xrv[6]=r1.z; xrv[7]=r1.w;
    }
    int b0 = off[d], b1 = off[d + 1];

    float m = -1e30f, den = 0.f, acc[8] = {};
    int s = (b0 < b1) ? srcs[b0] : 0;
    for (int i = b0; i < b1; i++) {
        int s_next = (i + 1 < b1) ? srcs[i + 1] : 0;
        const float4* p = (const float4*)(xl + (size_t)s * HC1 + lane * 8);
        float4 t0 = p[0], t1 = p[1];
        float t[8] = {t0.x, t0.y, t0.z, t0.w, t1.x, t1.y, t1.z, t1.w};
        float pp = 0.f;
        #pragma unroll
        for (int v = 0; v < 8; v++) {
            float g = t[v] + xrv[v];
            g = g > 0.f ? g : 0.2f * g;
            pp = fmaf(g, attv[v], pp);
        }
        pp += __shfl_xor_sync(0xFFFFFFFFu, pp, 1);
        pp += __shfl_xor_sync(0xFFFFFFFFu, pp, 2);
        pp += __shfl_xor_sync(0xFFFFFFFFu, pp, 4);
        float mn = fmaxf(m, pp);
        float sc = __expf(m - mn);
        float a  = __expf(pp - mn);
        den = den * sc + a;
        #pragma unroll
        for (int v = 0; v < 8; v++) acc[v] = fmaf(acc[v], sc, a * t[v]);
        m = mn;
        s = s_next;
    }

    float inv = 1.f / (den + 1e-16f);
    float ov[8];
    #pragma unroll
    for (int v = 0; v < 8; v++) {
        float x = acc[v] * inv + bias[lane * 8 + v];
        if (self) x += self[(size_t)d * C1 + (lane & 7) * 8 + v];
        ov[v] = x > 0.f ? x : (__expf(x) - 1.f);
    }
    float4* po = (float4*)(out + (size_t)d * HC1 + lane * 8);
    po[0] = make_float4(ov[0], ov[1], ov[2], ov[3]);
    po[1] = make_float4(ov[4], ov[5], ov[6], ov[7]);
}

// dual-relation layer-1 pass: warps [0,NG) -> sg, [NG, NG+NS) -> gs
__global__ void gat1_dual(const int* __restrict__ off_sg, const int* __restrict__ srcs_sg,
                          const float* __restrict__ xl_sg, const float* __restrict__ xr_sg,
                          const float* __restrict__ att_sg, const float* __restrict__ bias_sg,
                          float* __restrict__ out_sg,
                          const int* __restrict__ off_gs, const int* __restrict__ srcs_gs,
                          const float* __restrict__ xl_gs, const float* __restrict__ xr_gs,
                          const float* __restrict__ att_gs, const float* __restrict__ bias_gs,
                          const float* __restrict__ self_gs, float* __restrict__ out_gs) {
    int w = (blockIdx.x * blockDim.x + threadIdx.x) >> 5;
    int lane = threadIdx.x & 31;
    if (w < NG) {
        gat1_core(w, lane, off_sg, srcs_sg, xl_sg, xr_sg, att_sg, bias_sg, nullptr, out_sg);
    } else if (w < NG + NS) {
        gat1_core(w - NG, lane, off_gs, srcs_gs, xl_gs, xr_gs, att_gs, bias_gs, self_gs, out_gs);
    }
}

// ---------------- layer-3 GAT: warp per dst, head mean via shfl ----------------
__global__ void gat3_warp(const int* __restrict__ off, const int* __restrict__ srcs,
                          const float* __restrict__ xl, const float* __restrict__ xr,
                          const float* __restrict__ att, const float* __restrict__ bias3,
                          const float* __restrict__ sl3, float* __restrict__ out) {
    int d = (blockIdx.x * blockDim.x + threadIdx.x) >> 5;
    int lane = threadIdx.x & 31;
    if (d >= NS) return;

    float attv[16], xrv[16];
    {
        const float4* pa = (const float4*)(att + lane * 16);
        const float4* pr = (const float4*)(xr + (size_t)d * HC3 + lane * 16);
        #pragma unroll
        for (int q = 0; q < 4; q++) {
            float4 a = pa[q], r = pr[q];
            attv[q*4+0]=a.x; attv[q*4+1]=a.y; attv[q*4+2]=a.z; attv[q*4+3]=a.w;
            xrv[q*4+0]=r.x; xrv[q*4+1]=r.y; xrv[q*4+2]=r.z; xrv[q*4+3]=r.w;
        }
    }
    int b0 = off[d], b1 = off[d + 1];

    float m = -1e30f, den = 0.f, acc[16] = {};
    int s = (b0 < b1) ? srcs[b0] : 0;
    for (int i = b0; i < b1; i++) {
        int s_next = (i + 1 < b1) ? srcs[i + 1] : 0;
        const float4* p = (const float4*)(xl + (size_t)s * HC3 + lane * 16);
        float t[16];
        #pragma unroll
        for (int q = 0; q < 4; q++) {
            float4 tv = p[q];
            t[q*4+0]=tv.x; t[q*4+1]=tv.y; t[q*4+2]=tv.z; t[q*4+3]=tv.w;
        }
        float pp = 0.f;
        #pragma unroll
        for (int v = 0; v < 16; v++) {
            float g = t[v] + xrv[v];
            g = g > 0.f ? g : 0.2f * g;
            pp = fmaf(g, attv[v], pp);
        }
        pp += __shfl_xor_sync(0xFFFFFFFFu, pp, 1);
        pp += __shfl_xor_sync(0xFFFFFFFFu, pp, 2);
        pp += __shfl_xor_sync(0xFFFFFFFFu, pp, 4);
        float mn = fmaxf(m, pp);
        float sc = __expf(m - mn);
        float a  = __expf(pp - mn);
        den = den * sc + a;
        #pragma unroll
        for (int v = 0; v < 16; v++) acc[v] = fmaf(acc[v], sc, a * t[v]);
        m = mn;
        s = s_next;
    }

    float inv = 1.f / (den + 1e-16f);
    float ov[16];
    #pragma unroll
    for (int v = 0; v < 16; v++) {
        float hv = acc[v] * inv;
        hv += __shfl_xor_sync(0xFFFFFFFFu, hv, 8);
        hv += __shfl_xor_sync(0xFFFFFFFFu, hv, 16);
        ov[v] = 0.25f * hv;
    }
    if (lane < 8) {
        #pragma unroll
        for (int v = 0; v < 16; v++) {
            int c = lane * 16 + v;
            float x = ov[v] + bias3[c] + sl3[(size_t)d * C3 + c];
            ov[v] = x > 0.f ? x : (__expf(x) - 1.f);
        }
        float4* po = (float4*)(out + (size_t)d * C3 + lane * 16);
        #pragma unroll
        for (int q = 0; q < 4; q++)
            po[q] = make_float4(ov[q*4+0], ov[q*4+1], ov[q*4+2], ov[q*4+3]);
    }
}

// ---------------- host launch ----------------
static inline float* sym(const void* s) {
    void* p = nullptr;
    cudaGetSymbolAddress(&p, s);
    return (float*)p;
}
static inline int* symi(const void* s) {
    void* p = nullptr;
    cudaGetSymbolAddress(&p, s);
    return (int*)p;
}

extern "C" void kernel_launch(void* const* d_in, const int* in_sizes, int n_in,
                              void* d_out, int out_size) {
    const float* x_sample = (const float*)d_in[0];
    const float* x_gene   = (const float*)d_in[1];
    const int*   sg_src   = (const int*)d_in[2];
    const int*   sg_dst   = (const int*)d_in[3];
    const int*   gs_src   = (const int*)d_in[4];
    const int*   gs_dst   = (const int*)d_in[5];
    const float* Wl1_sg = (const float*)d_in[6];
    const float* bl1_sg = (const float*)d_in[7];
    const float* Wr1_sg = (const float*)d_in[8];
    const float* br1_sg = (const float*)d_in[9];
    const float* att1_sg  = (const float*)d_in[10];
    const float* bias1_sg = (const float*)d_in[11];
    const float* Wl1_gs = (const float*)d_in[12];
    const float* bl1_gs = (const float*)d_in[13];
    const float* Wr1_gs = (const float*)d_in[14];
    const float* br1_gs = (const float*)d_in[15];
    const float* att1_gs  = (const float*)d_in[16];
    const float* bias1_gs = (const float*)d_in[17];
    const float* Wl3_gs = (const float*)d_in[18];
    const float* bl3_gs = (const float*)d_in[19];
    const float* Wr3_gs = (const float*)d_in[20];
    const float* br3_gs = (const float*)d_in[21];
    const float* att3_gs  = (const float*)d_in[22];
    const float* bias3_gs = (const float*)d_in[23];
    const float* sl1_W = (const float*)d_in[24];
    const float* sl1_b = (const float*)d_in[25];
    const float* sl3_W = (const float*)d_in[26];
    const float* sl3_b = (const float*)d_in[27];
    float* out = (float*)d_out;

    float* xl_sg = sym(g_xl_sg);
    float* xr_sg = sym(g_xr_sg);
    float* xl_gs = sym(g_xl_gs);
    float* xr_gs = sym(g_xr_gs);
    float* x1_gene = sym(g_x1_gene);
    float* x1_sample = sym(g_x1_sample);
    float* sl1 = sym(g_sl1);
    float* xl3 = sym(g_xl3);
    float* xr3 = sym(g_xr3);
    float* sl3 = sym(g_sl3);
    float* w5p = sym(g_w5p);
    float* b5p = sym(g_b5p);
    int* deg_sg = symi(g_deg_sg);
    int* deg_gs = symi(g_deg_gs);
    int* off_sg = symi(g_off_sg);
    int* cur_sg = symi(g_cur_sg);
    int* srcs_sg = symi(g_srcs_sg);
    int* off_gs = symi(g_off_gs);
    int* cur_gs = symi(g_cur_gs);
    int* srcs_gs = symi(g_srcs_gs);

    cudaFuncSetAttribute(gemm_batch, cudaFuncAttributeMaxDynamicSharedMemorySize, GEMM_SMEM);

    dim3 tb(256);
    int eb = (NE + 255) / 256;

    // ----- CSR build -----
    zero2_kernel<<<(NG + 255) / 256, tb>>>(deg_sg, deg_gs);
    count2_kernel<<<eb, tb>>>(sg_dst, gs_dst, deg_sg, deg_gs);
    scan2_kernel<<<2, 1024>>>(deg_sg, off_sg, cur_sg, deg_gs, off_gs, cur_gs);
    scatter2_kernel<<<eb, tb>>>(sg_src, sg_dst, cur_sg, srcs_sg,
                                gs_src, gs_dst, cur_gs, srcs_gs);

    // ----- sl1 padding -----
    pad_w_kernel<<<(DIN * 128 + 255) / 256, tb>>>(sl1_W, sl1_b, w5p, b5p);

    const int MB_NS = NS / 128;            // 32
    const int MB_NG = (NG + 127) / 128;    // 157

    // ----- batch 1: all six layer-1 GEMMs in one launch -----
    {
        GemmBatch P;
        int blk = 0;
        P.seg[0] = {x_sample, Wl1_sg, bl1_sg, xl_sg, HC1, NS, HC1, 2, blk}; blk += 2 * MB_NS;
        P.seg[1] = {x_gene,   Wr1_sg, br1_sg, xr_sg, HC1, NG, HC1, 2, blk}; blk += 2 * MB_NG;
        P.seg[2] = {x_gene,   Wl1_gs, bl1_gs, xl_gs, HC1, NG, HC1, 2, blk}; blk += 2 * MB_NG;
        P.seg[3] = {x_sample, Wr1_gs, br1_gs, xr_gs, HC1, NS, HC1, 2, blk}; blk += 2 * MB_NS;
        P.seg[4] = {x_sample, w5p,    b5p,    sl1,   128, NS, C1,  1, blk}; blk += MB_NS;
        P.seg[5] = P.seg[4];
        P.nseg = 5;
        gemm_batch<<<blk, GEMM_THREADS, GEMM_SMEM>>>(P);
    }

    // ----- both layer-1 GAT passes in one launch -----
    gat1_dual<<<((NG + NS) * 32 + 255) / 256, tb>>>(
        off_sg, srcs_sg, xl_sg, xr_sg, att1_sg, bias1_sg, x1_gene,
        off_gs, srcs_gs, xl_gs, xr_gs, att1_gs, bias1_gs, sl1, x1_sample);

    // ----- batch 2: all three layer-3 GEMMs -----
    {
        GemmBatch P;
        int blk = 0;
        P.seg[0] = {x1_gene,   Wl3_gs, bl3_gs, xl3, HC3, NG, HC3, 4, blk}; blk += 4 * MB_NG;
        P.seg[1] = {x1_sample, Wr3_gs, br3_gs, xr3, HC3, NS, HC3, 4, blk}; blk += 4 * MB_NS;
        P.seg[2] = {x1_sample, sl3_W,  sl3_b,  sl3, C3,  NS, C3,  1, blk}; blk += MB_NS;
        P.seg[3] = P.seg[2];
        P.seg[4] = P.seg[2];
        P.seg[5] = P.seg[2];
        P.nseg = 3;
        gemm_batch<<<blk, GEMM_THREADS, GEMM_SMEM>>>(P);
    }

    // ----- layer-3 GAT + epilogue -----
    gat3_warp<<<(NS * 32 + 255) / 256, tb>>>(off_gs, srcs_gs, xl3, xr3, att3_gs, bias3_gs, sl3, out);
}

// round 10
// speedup vs baseline: 3.5107x; 1.8046x over previous
#include <cuda_runtime.h>
#include <cuda_fp16.h>
#include <mma.h>
#include <math.h>
#include <stddef.h>
#include <stdint.h>

using namespace nvcuda;

// Round 10 = Round 9 resubmission (container infra failure; kernel never ran).

// ---------------- problem constants ----------------
#define NS   4096
#define NG   20000
#define NGP  20096
#define NE   131072
#define DIN  256
#define H    4
#define C1   64
#define C3   128
#define HC1  256
#define HC3  512

// ---------------- device scratch ----------------
__device__ __align__(128) float g_xl_sg[NS * HC1];
__device__ __align__(128) float g_xr_sg[NGP * HC1];
__device__ __align__(128) float g_xl_gs[NGP * HC1];
__device__ __align__(128) float g_xr_gs[NS * HC1];
__device__ __align__(128) float g_sl1[NS * C1];
__device__ __align__(128) float g_xl3[NGP * HC3];
__device__ __align__(128) float g_xr3[NS * HC3];
__device__ __align__(128) float g_sl3[NS * C3];
__device__ __align__(128) float g_b5p[128];

// fp16 GEMM operands
__device__ __align__(128) __half g_hxs[NS * DIN];
__device__ __align__(128) __half g_hxg[NG * DIN];
__device__ __align__(128) __half g_hWl1sg[DIN * HC1];
__device__ __align__(128) __half g_hWr1sg[DIN * HC1];
__device__ __align__(128) __half g_hWl1gs[DIN * HC1];
__device__ __align__(128) __half g_hWr1gs[DIN * HC1];
__device__ __align__(128) __half g_hw5[DIN * 128];
__device__ __align__(128) __half g_hWl3[DIN * HC3];
__device__ __align__(128) __half g_hWr3[DIN * HC3];
__device__ __align__(128) __half g_hsl3W[DIN * C3];
__device__ __align__(128) __half g_x1h_gene[NG * HC1];
__device__ __align__(128) __half g_x1h_sample[NS * HC1];

__device__ int g_deg_sg[NG];
__device__ int g_deg_gs[NS];
__device__ int g_off_sg[NG + 1];
__device__ int g_cur_sg[NG];
__device__ int g_srcs_sg[NE];
__device__ int g_off_gs[NS + 1];
__device__ int g_cur_gs[NS];
__device__ int g_srcs_gs[NE];

// ---------------- helpers ----------------
__device__ __forceinline__ uint32_t smem_u32(const void* p) {
    uint32_t a;
    asm("{ .reg .u64 t; cvta.to.shared.u64 t, %1; cvt.u32.u64 %0, t; }" : "=r"(a) : "l"(p));
    return a;
}
#define CP_ASYNC16(dst, src) \
    asm volatile("cp.async.ca.shared.global [%0], [%1], 16;" :: "r"(dst), "l"(src))
#define CP_COMMIT() asm volatile("cp.async.commit_group;")
#define CP_WAIT(n)  asm volatile("cp.async.wait_group %0;" :: "n"(n))

// ---------------- fp32 -> fp16 conversion of all GEMM operands ----------------
__global__ void cvt_all(const float* __restrict__ xs, const float* __restrict__ xg,
                        const float* __restrict__ Wl1sg, const float* __restrict__ Wr1sg,
                        const float* __restrict__ Wl1gs, const float* __restrict__ Wr1gs,
                        const float* __restrict__ w5, const float* __restrict__ b5,
                        const float* __restrict__ Wl3, const float* __restrict__ Wr3,
                        const float* __restrict__ sl3W,
                        __half* __restrict__ hxs, __half* __restrict__ hxg,
                        __half* __restrict__ hWl1sg, __half* __restrict__ hWr1sg,
                        __half* __restrict__ hWl1gs, __half* __restrict__ hWr1gs,
                        __half* __restrict__ hw5, float* __restrict__ b5p,
                        __half* __restrict__ hWl3, __half* __restrict__ hWr3,
                        __half* __restrict__ hsl3W) {
    int i = blockIdx.x * blockDim.x + threadIdx.x;
    if (i < NS * DIN) hxs[i] = __float2half(xs[i]);
    if (i < NG * DIN) hxg[i] = __float2half(xg[i]);
    if (i < DIN * HC1) {
        hWl1sg[i] = __float2half(Wl1sg[i]);
        hWr1sg[i] = __float2half(Wr1sg[i]);
        hWl1gs[i] = __float2half(Wl1gs[i]);
        hWr1gs[i] = __float2half(Wr1gs[i]);
    }
    if (i < DIN * 128) {
        int k = i >> 7, c = i & 127;
        hw5[i] = (c < C1) ? __float2half(w5[k * C1 + c]) : __half(0.f);
        hsl3W[i] = __float2half(sl3W[i]);
    }
    if (i < 128) b5p[i] = (i < C1) ? b5[i] : 0.f;
    if (i < DIN * HC3) {
        hWl3[i] = __float2half(Wl3[i]);
        hWr3[i] = __float2half(Wr3[i]);
    }
}

// ---------------- batched fp16 WMMA GEMM (fp32 accum) ----------------
struct GemmSeg {
    const __half* A; const __half* B; const float* bias; float* C;
    int ldB; int M; int Nout; int nx; int blk0;
};
struct GemmBatch { GemmSeg seg[6]; int nseg; };

#define GEMM_THREADS 256
#define A_PITCH_H 72     // halves (144 B rows)
#define B_PITCH_H 136    // halves (272 B rows)
#define A_BUF_B   18432  // 128*72*2
#define B_BUF_B   17408  // 64*136*2
#define B_BASE_B  36864  // 2*A_BUF_B
#define GEMM_SMEM 71680  // 2*A + 2*B; epilogue staging 128*132*4=67584 fits

__global__ void __launch_bounds__(GEMM_THREADS) gemm_batch(GemmBatch P) {
    extern __shared__ char smc[];
    const int tid = threadIdx.x;
    const int wid = tid >> 5;
    const int warp_m = wid >> 1;
    const int warp_n = wid & 1;

    GemmSeg g = P.seg[0];
    #pragma unroll
    for (int i = 1; i < 6; i++)
        if (i < P.nseg && (int)blockIdx.x >= P.seg[i].blk0) g = P.seg[i];
    int lb = blockIdx.x - g.blk0;
    const int m0 = (lb / g.nx) * 128;
    const int col0 = (lb % g.nx) * 128;

    wmma::fragment<wmma::accumulator, 16, 16, 16, float> cfr[2][4];
    #pragma unroll
    for (int i = 0; i < 2; i++)
        #pragma unroll
        for (int t = 0; t < 4; t++) wmma::fill_fragment(cfr[i][t], 0.f);

    auto loadA = [&](int s, int b) {
        const __half* Ab = g.A + (size_t)m0 * 256 + s * 64;
        char* dst = smc + b * A_BUF_B;
        #pragma unroll
        for (int i = 0; i < 4; i++) {
            int ch = tid + i * 256;
            int r = ch >> 3, c8 = ch & 7;
            char* dp = dst + r * 144 + c8 * 16;
            if (m0 + r < g.M) {
                CP_ASYNC16(smem_u32(dp), Ab + (size_t)r * 256 + c8 * 8);
            } else {
                *(uint4*)dp = make_uint4(0, 0, 0, 0);
            }
        }
    };
    auto loadB = [&](int s, int b) {
        const __half* Bb = g.B + (size_t)(s * 64) * g.ldB + col0;
        char* dst = smc + B_BASE_B + b * B_BUF_B;
        #pragma unroll
        for (int i = 0; i < 4; i++) {
            int ch = tid + i * 256;
            int r = ch >> 4, c8 = ch & 15;
            CP_ASYNC16(smem_u32(dst + r * 272 + c8 * 16), Bb + (size_t)r * g.ldB + c8 * 8);
        }
    };

    loadA(0, 0); loadB(0, 0);
    CP_COMMIT();

    #pragma unroll 1
    for (int s = 0; s < 4; s++) {
        int b = s & 1;
        if (s < 3) { loadA(s + 1, b ^ 1); loadB(s + 1, b ^ 1); CP_COMMIT(); }
        if (s < 3) { CP_WAIT(1); } else { CP_WAIT(0); }
        __syncthreads();

        const __half* As = (const __half*)(smc + b * A_BUF_B) + warp_m * 32 * A_PITCH_H;
        const __half* Bs = (const __half*)(smc + B_BASE_B + b * B_BUF_B);
        #pragma unroll
        for (int kk = 0; kk < 4; kk++) {
            wmma::fragment<wmma::matrix_a, 16, 16, 16, __half, wmma::row_major> af[2];
            wmma::load_matrix_sync(af[0], As + kk * 16, A_PITCH_H);
            wmma::load_matrix_sync(af[1], As + 16 * A_PITCH_H + kk * 16, A_PITCH_H);
            #pragma unroll
            for (int t = 0; t < 4; t++) {
                wmma::fragment<wmma::matrix_b, 16, 16, 16, __half, wmma::row_major> bf;
                wmma::load_matrix_sync(bf, Bs + kk * 16 * B_PITCH_H + warp_n * 64 + t * 16, B_PITCH_H);
                wmma::mma_sync(cfr[0][t], af[0], bf, cfr[0][t]);
                wmma::mma_sync(cfr[1][t], af[1], bf, cfr[1][t]);
            }
        }
        __syncthreads();
    }

    float* stg = (float*)smc;
    #pragma unroll
    for (int i = 0; i < 2; i++)
        #pragma unroll
        for (int t = 0; t < 4; t++)
            wmma::store_matrix_sync(stg + (warp_m * 32 + i * 16) * 132 + warp_n * 64 + t * 16,
                                    cfr[i][t], 132, wmma::mem_row_major);
    __syncthreads();

    #pragma unroll
    for (int id = tid; id < 128 * 32; id += 256) {
        int r = id >> 5;
        int c = (id & 31) * 4;
        if (col0 + c < g.Nout) {
            float4 v = *(const float4*)(stg + r * 132 + c);
            float4 bv = *(const float4*)(g.bias + col0 + c);
            v.x += bv.x; v.y += bv.y; v.z += bv.z; v.w += bv.w;
            *(float4*)(g.C + (size_t)(m0 + r) * g.Nout + col0 + c) = v;
        }
    }
}

// ---------------- CSR build ----------------
__global__ void zero2_kernel(int* __restrict__ dsg, int* __restrict__ dgs) {
    int i = blockIdx.x * blockDim.x + threadIdx.x;
    if (i < NG) dsg[i] = 0;
    if (i < NS) dgs[i] = 0;
}

__global__ void count2_kernel(const int* __restrict__ sg_dst, const int* __restrict__ gs_dst,
                              int* __restrict__ dsg, int* __restrict__ dgs) {
    int e = blockIdx.x * blockDim.x + threadIdx.x;
    if (e < NE) {
        atomicAdd(&dsg[sg_dst[e]], 1);
        atomicAdd(&dgs[gs_dst[e]], 1);
    }
}

__global__ void scan2_kernel(const int* __restrict__ dsg, int* __restrict__ off_sg, int* __restrict__ cur_sg,
                             const int* __restrict__ dgs, int* __restrict__ off_gs, int* __restrict__ cur_gs) {
    const int* deg = (blockIdx.x == 0) ? dsg : dgs;
    int* off = (blockIdx.x == 0) ? off_sg : off_gs;
    int* cur = (blockIdx.x == 0) ? cur_sg : cur_gs;
    int n = (blockIdx.x == 0) ? NG : NS;
    __shared__ int wsum[32];
    int tid = threadIdx.x, lane = tid & 31, wid = tid >> 5;
    int carry = 0;
    for (int base = 0; base < n; base += 1024) {
        int i = base + tid;
        int v = (i < n) ? deg[i] : 0;
        int x = v;
        #pragma unroll
        for (int o = 1; o < 32; o <<= 1) {
            int t = __shfl_up_sync(0xFFFFFFFFu, x, o);
            if (lane >= o) x += t;
        }
        if (lane == 31) wsum[wid] = x;
        __syncthreads();
        if (wid == 0) {
            int y = wsum[lane];
            #pragma unroll
            for (int o = 1; o < 32; o <<= 1) {
                int t = __shfl_up_sync(0xFFFFFFFFu, y, o);
                if (lane >= o) y += t;
            }
            wsum[lane] = y;
        }
        __syncthreads();
        int pre = (wid > 0) ? wsum[wid - 1] : 0;
        if (i < n) {
            int e = carry + pre + x - v;
            off[i] = e;
            cur[i] = e;
        }
        int total = wsum[31];
        __syncthreads();
        carry += total;
    }
    if (tid == 0) off[n] = carry;
}

__global__ void scatter2_kernel(const int* __restrict__ sg_src, const int* __restrict__ sg_dst,
                                int* __restrict__ cur_sg, int* __restrict__ srcs_sg,
                                const int* __restrict__ gs_src, const int* __restrict__ gs_dst,
                                int* __restrict__ cur_gs, int* __restrict__ srcs_gs) {
    int e = blockIdx.x * blockDim.x + threadIdx.x;
    if (e < NE) {
        int p = atomicAdd(&cur_sg[sg_dst[e]], 1);
        srcs_sg[p] = sg_src[e];
        int q = atomicAdd(&cur_gs[gs_dst[e]], 1);
        srcs_gs[q] = gs_src[e];
    }
}

// ---------------- layer-1 GAT core: warp per dst, 4 heads, half output ----------------
__device__ __forceinline__ void gat1_core(int d, int lane,
                                          const int* __restrict__ off, const int* __restrict__ srcs,
                                          const float* __restrict__ xl, const float* __restrict__ xr,
                                          const float* __restrict__ att, const float* __restrict__ bias,
                                          const float* __restrict__ self, __half* __restrict__ out) {
    float attv[8], xrv[8];
    {
        const float4* pa = (const float4*)(att + lane * 8);
        const float4* pr = (const float4*)(xr + (size_t)d * HC1 + lane * 8);
        float4 a0 = pa[0], a1 = pa[1], r0 = pr[0], r1 = pr[1];
        attv[0]=a0.x; attv[1]=a0.y; attv[2]=a0.z; attv[3]=a0.w;
        attv[4]=a1.x; attv[5]=a1.y; attv[6]=a1.z; attv[7]=a1.w;
        xrv[0]=r0.x; xrv[1]=r0.y; xrv[2]=r0.z; xrv[3]=r0.w;
        xrv[4]=r1.x; xrv[5]=r1.y; xrv[6]=r1.z; xrv[7]=r1.w;
    }
    int b0 = off[d], b1 = off[d + 1];

    float m = -1e30f, den = 0.f, acc[8] = {};
    int s = (b0 < b1) ? srcs[b0] : 0;
    for (int i = b0; i < b1; i++) {
        int s_next = (i + 1 < b1) ? srcs[i + 1] : 0;
        const float4* p = (const float4*)(xl + (size_t)s * HC1 + lane * 8);
        float4 t0 = p[0], t1 = p[1];
        float t[8] = {t0.x, t0.y, t0.z, t0.w, t1.x, t1.y, t1.z, t1.w};
        float pp = 0.f;
        #pragma unroll
        for (int v = 0; v < 8; v++) {
            float g = t[v] + xrv[v];
            g = g > 0.f ? g : 0.2f * g;
            pp = fmaf(g, attv[v], pp);
        }
        pp += __shfl_xor_sync(0xFFFFFFFFu, pp, 1);
        pp += __shfl_xor_sync(0xFFFFFFFFu, pp, 2);
        pp += __shfl_xor_sync(0xFFFFFFFFu, pp, 4);
        float mn = fmaxf(m, pp);
        float sc = __expf(m - mn);
        float a  = __expf(pp - mn);
        den = den * sc + a;
        #pragma unroll
        for (int v = 0; v < 8; v++) acc[v] = fmaf(acc[v], sc, a * t[v]);
        m = mn;
        s = s_next;
    }

    float inv = 1.f / (den + 1e-16f);
    float ov[8];
    #pragma unroll
    for (int v = 0; v < 8; v++) {
        float x = acc[v] * inv + bias[lane * 8 + v];
        if (self) x += self[(size_t)d * C1 + (lane & 7) * 8 + v];
        ov[v] = x > 0.f ? x : (__expf(x) - 1.f);
    }
    __half2 hv[4];
    #pragma unroll
    for (int j = 0; j < 4; j++) hv[j] = __floats2half2_rn(ov[2 * j], ov[2 * j + 1]);
    *(uint4*)(out + (size_t)d * HC1 + lane * 8) = *(uint4*)hv;
}

__global__ void gat1_dual(const int* __restrict__ off_sg, const int* __restrict__ srcs_sg,
                          const float* __restrict__ xl_sg, const float* __restrict__ xr_sg,
                          const float* __restrict__ att_sg, const float* __restrict__ bias_sg,
                          __half* __restrict__ out_sg,
                          const int* __restrict__ off_gs, const int* __restrict__ srcs_gs,
                          const float* __restrict__ xl_gs, const float* __restrict__ xr_gs,
                          const float* __restrict__ att_gs, const float* __restrict__ bias_gs,
                          const float* __restrict__ self_gs, __half* __restrict__ out_gs) {
    int w = (blockIdx.x * blockDim.x + threadIdx.x) >> 5;
    int lane = threadIdx.x & 31;
    if (w < NG) {
        gat1_core(w, lane, off_sg, srcs_sg, xl_sg, xr_sg, att_sg, bias_sg, nullptr, out_sg);
    } else if (w < NG + NS) {
        gat1_core(w - NG, lane, off_gs, srcs_gs, xl_gs, xr_gs, att_gs, bias_gs, self_gs, out_gs);
    }
}

// ---------------- layer-3 GAT: warp per dst, head mean via shfl ----------------
__global__ void gat3_warp(const int* __restrict__ off, const int* __restrict__ srcs,
                          const float* __restrict__ xl, const float* __restrict__ xr,
                          const float* __restrict__ att, const float* __restrict__ bias3,
                          const float* __restrict__ sl3, float* __restrict__ out) {
    int d = (blockIdx.x * blockDim.x + threadIdx.x) >> 5;
    int lane = threadIdx.x & 31;
    if (d >= NS) return;

    float attv[16], xrv[16];
    {
        const float4* pa = (const float4*)(att + lane * 16);
        const float4* pr = (const float4*)(xr + (size_t)d * HC3 + lane * 16);
        #pragma unroll
        for (int q = 0; q < 4; q++) {
            float4 a = pa[q], r = pr[q];
            attv[q*4+0]=a.x; attv[q*4+1]=a.y; attv[q*4+2]=a.z; attv[q*4+3]=a.w;
            xrv[q*4+0]=r.x; xrv[q*4+1]=r.y; xrv[q*4+2]=r.z; xrv[q*4+3]=r.w;
        }
    }
    int b0 = off[d], b1 = off[d + 1];

    float m = -1e30f, den = 0.f, acc[16] = {};
    int s = (b0 < b1) ? srcs[b0] : 0;
    for (int i = b0; i < b1; i++) {
        int s_next = (i + 1 < b1) ? srcs[i + 1] : 0;
        const float4* p = (const float4*)(xl + (size_t)s * HC3 + lane * 16);
        float t[16];
        #pragma unroll
        for (int q = 0; q < 4; q++) {
            float4 tv = p[q];
            t[q*4+0]=tv.x; t[q*4+1]=tv.y; t[q*4+2]=tv.z; t[q*4+3]=tv.w;
        }
        float pp = 0.f;
        #pragma unroll
        for (int v = 0; v < 16; v++) {
            float g = t[v] + xrv[v];
            g = g > 0.f ? g : 0.2f * g;
            pp = fmaf(g, attv[v], pp);
        }
        pp += __shfl_xor_sync(0xFFFFFFFFu, pp, 1);
        pp += __shfl_xor_sync(0xFFFFFFFFu, pp, 2);
        pp += __shfl_xor_sync(0xFFFFFFFFu, pp, 4);
        float mn = fmaxf(m, pp);
        float sc = __expf(m - mn);
        float a  = __expf(pp - mn);
        den = den * sc + a;
        #pragma unroll
        for (int v = 0; v < 16; v++) acc[v] = fmaf(acc[v], sc, a * t[v]);
        m = mn;
        s = s_next;
    }

    float inv = 1.f / (den + 1e-16f);
    float ov[16];
    #pragma unroll
    for (int v = 0; v < 16; v++) {
        float hv = acc[v] * inv;
        hv += __shfl_xor_sync(0xFFFFFFFFu, hv, 8);
        hv += __shfl_xor_sync(0xFFFFFFFFu, hv, 16);
        ov[v] = 0.25f * hv;
    }
    if (lane < 8) {
        #pragma unroll
        for (int v = 0; v < 16; v++) {
            int c = lane * 16 + v;
            float x = ov[v] + bias3[c] + sl3[(size_t)d * C3 + c];
            ov[v] = x > 0.f ? x : (__expf(x) - 1.f);
        }
        float4* po = (float4*)(out + (size_t)d * C3 + lane * 16);
        #pragma unroll
        for (int q = 0; q < 4; q++)
            po[q] = make_float4(ov[q*4+0], ov[q*4+1], ov[q*4+2], ov[q*4+3]);
    }
}

// ---------------- host launch ----------------
static inline float* sym(const void* s) {
    void* p = nullptr;
    cudaGetSymbolAddress(&p, s);
    return (float*)p;
}
static inline __half* symh(const void* s) {
    void* p = nullptr;
    cudaGetSymbolAddress(&p, s);
    return (__half*)p;
}
static inline int* symi(const void* s) {
    void* p = nullptr;
    cudaGetSymbolAddress(&p, s);
    return (int*)p;
}

extern "C" void kernel_launch(void* const* d_in, const int* in_sizes, int n_in,
                              void* d_out, int out_size) {
    const float* x_sample = (const float*)d_in[0];
    const float* x_gene   = (const float*)d_in[1];
    const int*   sg_src   = (const int*)d_in[2];
    const int*   sg_dst   = (const int*)d_in[3];
    const int*   gs_src   = (const int*)d_in[4];
    const int*   gs_dst   = (const int*)d_in[5];
    const float* Wl1_sg = (const float*)d_in[6];
    const float* bl1_sg = (const float*)d_in[7];
    const float* Wr1_sg = (const float*)d_in[8];
    const float* br1_sg = (const float*)d_in[9];
    const float* att1_sg  = (const float*)d_in[10];
    const float* bias1_sg = (const float*)d_in[11];
    const float* Wl1_gs = (const float*)d_in[12];
    const float* bl1_gs = (const float*)d_in[13];
    const float* Wr1_gs = (const float*)d_in[14];
    const float* br1_gs = (const float*)d_in[15];
    const float* att1_gs  = (const float*)d_in[16];
    const float* bias1_gs = (const float*)d_in[17];
    const float* Wl3_gs = (const float*)d_in[18];
    const float* bl3_gs = (const float*)d_in[19];
    const float* Wr3_gs = (const float*)d_in[20];
    const float* br3_gs = (const float*)d_in[21];
    const float* att3_gs  = (const float*)d_in[22];
    const float* bias3_gs = (const float*)d_in[23];
    const float* sl1_W = (const float*)d_in[24];
    const float* sl1_b = (const float*)d_in[25];
    const float* sl3_W = (const float*)d_in[26];
    const float* sl3_b = (const float*)d_in[27];
    float* out = (float*)d_out;

    float* xl_sg = sym(g_xl_sg);
    float* xr_sg = sym(g_xr_sg);
    float* xl_gs = sym(g_xl_gs);
    float* xr_gs = sym(g_xr_gs);
    float* sl1 = sym(g_sl1);
    float* xl3 = sym(g_xl3);
    float* xr3 = sym(g_xr3);
    float* sl3 = sym(g_sl3);
    float* b5p = sym(g_b5p);
    __half* hxs = symh(g_hxs);
    __half* hxg = symh(g_hxg);
    __half* hWl1sg = symh(g_hWl1sg);
    __half* hWr1sg = symh(g_hWr1sg);
    __half* hWl1gs = symh(g_hWl1gs);
    __half* hWr1gs = symh(g_hWr1gs);
    __half* hw5 = symh(g_hw5);
    __half* hWl3 = symh(g_hWl3);
    __half* hWr3 = symh(g_hWr3);
    __half* hsl3W = symh(g_hsl3W);
    __half* x1h_gene = symh(g_x1h_gene);
    __half* x1h_sample = symh(g_x1h_sample);
    int* deg_sg = symi(g_deg_sg);
    int* deg_gs = symi(g_deg_gs);
    int* off_sg = symi(g_off_sg);
    int* cur_sg = symi(g_cur_sg);
    int* srcs_sg = symi(g_srcs_sg);
    int* off_gs = symi(g_off_gs);
    int* cur_gs = symi(g_cur_gs);
    int* srcs_gs = symi(g_srcs_gs);

    cudaFuncSetAttribute(gemm_batch, cudaFuncAttributeMaxDynamicSharedMemorySize, GEMM_SMEM);

    dim3 tb(256);
    int eb = (NE + 255) / 256;

    // ----- CSR build -----
    zero2_kernel<<<(NG + 255) / 256, tb>>>(deg_sg, deg_gs);
    count2_kernel<<<eb, tb>>>(sg_dst, gs_dst, deg_sg, deg_gs);
    scan2_kernel<<<2, 1024>>>(deg_sg, off_sg, cur_sg, deg_gs, off_gs, cur_gs);
    scatter2_kernel<<<eb, tb>>>(sg_src, sg_dst, cur_sg, srcs_sg,
                                gs_src, gs_dst, cur_gs, srcs_gs);

    // ----- fp16 conversion of all GEMM operands -----
    cvt_all<<<(NG * DIN + 255) / 256, tb>>>(
        x_sample, x_gene, Wl1_sg, Wr1_sg, Wl1_gs, Wr1_gs, sl1_W, sl1_b,
        Wl3_gs, Wr3_gs, sl3_W,
        hxs, hxg, hWl1sg, hWr1sg, hWl1gs, hWr1gs, hw5, b5p, hWl3, hWr3, hsl3W);

    const int MB_NS = NS / 128;            // 32
    const int MB_NG = (NG + 127) / 128;    // 157

    // ----- batch 1: all six layer-1 GEMMs -----
    {
        GemmBatch P;
        int blk = 0;
        P.seg[0] = {hxs, hWl1sg, bl1_sg, xl_sg, HC1, NS, HC1, 2, blk}; blk += 2 * MB_NS;
        P.seg[1] = {hxg, hWr1sg, br1_sg, xr_sg, HC1, NG, HC1, 2, blk}; blk += 2 * MB_NG;
        P.seg[2] = {hxg, hWl1gs, bl1_gs, xl_gs, HC1, NG, HC1, 2, blk}; blk += 2 * MB_NG;
        P.seg[3] = {hxs, hWr1gs, br1_gs, xr_gs, HC1, NS, HC1, 2, blk}; blk += 2 * MB_NS;
        P.seg[4] = {hxs, hw5,    b5p,    sl1,   128, NS, C1,  1, blk}; blk += MB_NS;
        P.seg[5] = P.seg[4];
        P.nseg = 5;
        gemm_batch<<<blk, GEMM_THREADS, GEMM_SMEM>>>(P);
    }

    // ----- both layer-1 GAT passes (write half) -----
    gat1_dual<<<((NG + NS) * 32 + 255) / 256, tb>>>(
        off_sg, srcs_sg, xl_sg, xr_sg, att1_sg, bias1_sg, x1h_gene,
        off_gs, srcs_gs, xl_gs, xr_gs, att1_gs, bias1_gs, sl1, x1h_sample);

    // ----- batch 2: all three layer-3 GEMMs -----
    {
        GemmBatch P;
        int blk = 0;
        P.seg[0] = {x1h_gene,   hWl3,  bl3_gs, xl3, HC3, NG, HC3, 4, blk}; blk += 4 * MB_NG;
        P.seg[1] = {x1h_sample, hWr3,  br3_gs, xr3, HC3, NS, HC3, 4, blk}; blk += 4 * MB_NS;
        P.seg[2] = {x1h_sample, hsl3W, sl3_b,  sl3, C3,  NS, C3,  1, blk}; blk += MB_NS;
        P.seg[3] = P.seg[2];
        P.seg[4] = P.seg[2];
        P.seg[5] = P.seg[2];
        P.nseg = 3;
        gemm_batch<<<blk, GEMM_THREADS, GEMM_SMEM>>>(P);
    }

    // ----- layer-3 GAT + epilogue -----
    gat3_warp<<<(NS * 32 + 255) / 256, tb>>>(off_gs, srcs_gs, xl3, xr3, att3_gs, bias3_gs, sl3, out);
}

// round 11
// speedup vs baseline: 3.5310x; 1.0058x over previous
#include <cuda_runtime.h>
#include <cuda_fp16.h>
#include <mma.h>
#include <math.h>
#include <stddef.h>
#include <stdint.h>

using namespace nvcuda;

// Round 10 = Round 9 resubmission (container infra failure; kernel never ran).

// ---------------- problem constants ----------------
#define NS   4096
#define NG   20000
#define NGP  20096
#define NE   131072
#define DIN  256
#define H    4
#define C1   64
#define C3   128
#define HC1  256
#define HC3  512

// ---------------- device scratch ----------------
__device__ __align__(128) float g_xl_sg[NS * HC1];
__device__ __align__(128) float g_xr_sg[NGP * HC1];
__device__ __align__(128) float g_xl_gs[NGP * HC1];
__device__ __align__(128) float g_xr_gs[NS * HC1];
__device__ __align__(128) float g_sl1[NS * C1];
__device__ __align__(128) float g_xl3[NGP * HC3];
__device__ __align__(128) float g_xr3[NS * HC3];
__device__ __align__(128) float g_sl3[NS * C3];
__device__ __align__(128) float g_b5p[128];

// fp16 GEMM operands
__device__ __align__(128) __half g_hxs[NS * DIN];
__device__ __align__(128) __half g_hxg[NG * DIN];
__device__ __align__(128) __half g_hWl1sg[DIN * HC1];
__device__ __align__(128) __half g_hWr1sg[DIN * HC1];
__device__ __align__(128) __half g_hWl1gs[DIN * HC1];
__device__ __align__(128) __half g_hWr1gs[DIN * HC1];
__device__ __align__(128) __half g_hw5[DIN * 128];
__device__ __align__(128) __half g_hWl3[DIN * HC3];
__device__ __align__(128) __half g_hWr3[DIN * HC3];
__device__ __align__(128) __half g_hsl3W[DIN * C3];
__device__ __align__(128) __half g_x1h_gene[NG * HC1];
__device__ __align__(128) __half g_x1h_sample[NS * HC1];

__device__ int g_deg_sg[NG];
__device__ int g_deg_gs[NS];
__device__ int g_off_sg[NG + 1];
__device__ int g_cur_sg[NG];
__device__ int g_srcs_sg[NE];
__device__ int g_off_gs[NS + 1];
__device__ int g_cur_gs[NS];
__device__ int g_srcs_gs[NE];

// ---------------- helpers ----------------
__device__ __forceinline__ uint32_t smem_u32(const void* p) {
    uint32_t a;
    asm("{ .reg .u64 t; cvta.to.shared.u64 t, %1; cvt.u32.u64 %0, t; }" : "=r"(a) : "l"(p));
    return a;
}
#define CP_ASYNC16(dst, src) \
    asm volatile("cp.async.ca.shared.global [%0], [%1], 16;" :: "r"(dst), "l"(src))
#define CP_COMMIT() asm volatile("cp.async.commit_group;")
#define CP_WAIT(n)  asm volatile("cp.async.wait_group %0;" :: "n"(n))

// ---------------- fp32 -> fp16 conversion of all GEMM operands ----------------
__global__ void cvt_all(const float* __restrict__ xs, const float* __restrict__ xg,
                        const float* __restrict__ Wl1sg, const float* __restrict__ Wr1sg,
                        const float* __restrict__ Wl1gs, const float* __restrict__ Wr1gs,
                        const float* __restrict__ w5, const float* __restrict__ b5,
                        const float* __restrict__ Wl3, const float* __restrict__ Wr3,
                        const float* __restrict__ sl3W,
                        __half* __restrict__ hxs, __half* __restrict__ hxg,
                        __half* __restrict__ hWl1sg, __half* __restrict__ hWr1sg,
                        __half* __restrict__ hWl1gs, __half* __restrict__ hWr1gs,
                        __half* __restrict__ hw5, float* __restrict__ b5p,
                        __half* __restrict__ hWl3, __half* __restrict__ hWr3,
                        __half* __restrict__ hsl3W) {
    int i = blockIdx.x * blockDim.x + threadIdx.x;
    if (i < NS * DIN) hxs[i] = __float2half(xs[i]);
    if (i < NG * DIN) hxg[i] = __float2half(xg[i]);
    if (i < DIN * HC1) {
        hWl1sg[i] = __float2half(Wl1sg[i]);
        hWr1sg[i] = __float2half(Wr1sg[i]);
        hWl1gs[i] = __float2half(Wl1gs[i]);
        hWr1gs[i] = __float2half(Wr1gs[i]);
    }
    if (i < DIN * 128) {
        int k = i >> 7, c = i & 127;
        hw5[i] = (c < C1) ? __float2half(w5[k * C1 + c]) : __half(0.f);
        hsl3W[i] = __float2half(sl3W[i]);
    }
    if (i < 128) b5p[i] = (i < C1) ? b5[i] : 0.f;
    if (i < DIN * HC3) {
        hWl3[i] = __float2half(Wl3[i]);
        hWr3[i] = __float2half(Wr3[i]);
    }
}

// ---------------- batched fp16 WMMA GEMM (fp32 accum) ----------------
struct GemmSeg {
    const __half* A; const __half* B; const float* bias; float* C;
    int ldB; int M; int Nout; int nx; int blk0;
};
struct GemmBatch { GemmSeg seg[6]; int nseg; };

#define GEMM_THREADS 256
#define A_PITCH_H 72     // halves (144 B rows)
#define B_PITCH_H 136    // halves (272 B rows)
#define A_BUF_B   18432  // 128*72*2
#define B_BUF_B   17408  // 64*136*2
#define B_BASE_B  36864  // 2*A_BUF_B
#define GEMM_SMEM 71680  // 2*A + 2*B; epilogue staging 128*132*4=67584 fits

__global__ void __launch_bounds__(GEMM_THREADS) gemm_batch(GemmBatch P) {
    extern __shared__ char smc[];
    const int tid = threadIdx.x;
    const int wid = tid >> 5;
    const int warp_m = wid >> 1;
    const int warp_n = wid & 1;

    GemmSeg g = P.seg[0];
    #pragma unroll
    for (int i = 1; i < 6; i++)
        if (i < P.nseg && (int)blockIdx.x >= P.seg[i].blk0) g = P.seg[i];
    int lb = blockIdx.x - g.blk0;
    const int m0 = (lb / g.nx) * 128;
    const int col0 = (lb % g.nx) * 128;

    wmma::fragment<wmma::accumulator, 16, 16, 16, float> cfr[2][4];
    #pragma unroll
    for (int i = 0; i < 2; i++)
        #pragma unroll
        for (int t = 0; t < 4; t++) wmma::fill_fragment(cfr[i][t], 0.f);

    auto loadA = [&](int s, int b) {
        const __half* Ab = g.A + (size_t)m0 * 256 + s * 64;
        char* dst = smc + b * A_BUF_B;
        #pragma unroll
        for (int i = 0; i < 4; i++) {
            int ch = tid + i * 256;
            int r = ch >> 3, c8 = ch & 7;
            char* dp = dst + r * 144 + c8 * 16;
            if (m0 + r < g.M) {
                CP_ASYNC16(smem_u32(dp), Ab + (size_t)r * 256 + c8 * 8);
            } else {
                *(uint4*)dp = make_uint4(0, 0, 0, 0);
            }
        }
    };
    auto loadB = [&](int s, int b) {
        const __half* Bb = g.B + (size_t)(s * 64) * g.ldB + col0;
        char* dst = smc + B_BASE_B + b * B_BUF_B;
        #pragma unroll
        for (int i = 0; i < 4; i++) {
            int ch = tid + i * 256;
            int r = ch >> 4, c8 = ch & 15;
            CP_ASYNC16(smem_u32(dst + r * 272 + c8 * 16), Bb + (size_t)r * g.ldB + c8 * 8);
        }
    };

    loadA(0, 0); loadB(0, 0);
    CP_COMMIT();

    #pragma unroll 1
    for (int s = 0; s < 4; s++) {
        int b = s & 1;
        if (s < 3) { loadA(s + 1, b ^ 1); loadB(s + 1, b ^ 1); CP_COMMIT(); }
        if (s < 3) { CP_WAIT(1); } else { CP_WAIT(0); }
        __syncthreads();

        const __half* As = (const __half*)(smc + b * A_BUF_B) + warp_m * 32 * A_PITCH_H;
        const __half* Bs = (const __half*)(smc + B_BASE_B + b * B_BUF_B);
        #pragma unroll
        for (int kk = 0; kk < 4; kk++) {
            wmma::fragment<wmma::matrix_a, 16, 16, 16, __half, wmma::row_major> af[2];
            wmma::load_matrix_sync(af[0], As + kk * 16, A_PITCH_H);
            wmma::load_matrix_sync(af[1], As + 16 * A_PITCH_H + kk * 16, A_PITCH_H);
            #pragma unroll
            for (int t = 0; t < 4; t++) {
                wmma::fragment<wmma::matrix_b, 16, 16, 16, __half, wmma::row_major> bf;
                wmma::load_matrix_sync(bf, Bs + kk * 16 * B_PITCH_H + warp_n * 64 + t * 16, B_PITCH_H);
                wmma::mma_sync(cfr[0][t], af[0], bf, cfr[0][t]);
                wmma::mma_sync(cfr[1][t], af[1], bf, cfr[1][t]);
            }
        }
        __syncthreads();
    }

    float* stg = (float*)smc;
    #pragma unroll
    for (int i = 0; i < 2; i++)
        #pragma unroll
        for (int t = 0; t < 4; t++)
            wmma::store_matrix_sync(stg + (warp_m * 32 + i * 16) * 132 + warp_n * 64 + t * 16,
                                    cfr[i][t], 132, wmma::mem_row_major);
    __syncthreads();

    #pragma unroll
    for (int id = tid; id < 128 * 32; id += 256) {
        int r = id >> 5;
        int c = (id & 31) * 4;
        if (col0 + c < g.Nout) {
            float4 v = *(const float4*)(stg + r * 132 + c);
            float4 bv = *(const float4*)(g.bias + col0 + c);
            v.x += bv.x; v.y += bv.y; v.z += bv.z; v.w += bv.w;
            *(float4*)(g.C + (size_t)(m0 + r) * g.Nout + col0 + c) = v;
        }
    }
}

// ---------------- CSR build ----------------
__global__ void zero2_kernel(int* __restrict__ dsg, int* __restrict__ dgs) {
    int i = blockIdx.x * blockDim.x + threadIdx.x;
    if (i < NG) dsg[i] = 0;
    if (i < NS) dgs[i] = 0;
}

__global__ void count2_kernel(const int* __restrict__ sg_dst, const int* __restrict__ gs_dst,
                              int* __restrict__ dsg, int* __restrict__ dgs) {
    int e = blockIdx.x * blockDim.x + threadIdx.x;
    if (e < NE) {
        atomicAdd(&dsg[sg_dst[e]], 1);
        atomicAdd(&dgs[gs_dst[e]], 1);
    }
}

__global__ void scan2_kernel(const int* __restrict__ dsg, int* __restrict__ off_sg, int* __restrict__ cur_sg,
                             const int* __restrict__ dgs, int* __restrict__ off_gs, int* __restrict__ cur_gs) {
    const int* deg = (blockIdx.x == 0) ? dsg : dgs;
    int* off = (blockIdx.x == 0) ? off_sg : off_gs;
    int* cur = (blockIdx.x == 0) ? cur_sg : cur_gs;
    int n = (blockIdx.x == 0) ? NG : NS;
    __shared__ int wsum[32];
    int tid = threadIdx.x, lane = tid & 31, wid = tid >> 5;
    int carry = 0;
    for (int base = 0; base < n; base += 1024) {
        int i = base + tid;
        int v = (i < n) ? deg[i] : 0;
        int x = v;
        #pragma unroll
        for (int o = 1; o < 32; o <<= 1) {
            int t = __shfl_up_sync(0xFFFFFFFFu, x, o);
            if (lane >= o) x += t;
        }
        if (lane == 31) wsum[wid] = x;
        __syncthreads();
        if (wid == 0) {
            int y = wsum[lane];
            #pragma unroll
            for (int o = 1; o < 32; o <<= 1) {
                int t = __shfl_up_sync(0xFFFFFFFFu, y, o);
                if (lane >= o) y += t;
            }
            wsum[lane] = y;
        }
        __syncthreads();
        int pre = (wid > 0) ? wsum[wid - 1] : 0;
        if (i < n) {
            int e = carry + pre + x - v;
            off[i] = e;
            cur[i] = e;
        }
        int total = wsum[31];
        __syncthreads();
        carry += total;
    }
    if (tid == 0) off[n] = carry;
}

__global__ void scatter2_kernel(const int* __restrict__ sg_src, const int* __restrict__ sg_dst,
                                int* __restrict__ cur_sg, int* __restrict__ srcs_sg,
                                const int* __restrict__ gs_src, const int* __restrict__ gs_dst,
                                int* __restrict__ cur_gs, int* __restrict__ srcs_gs) {
    int e = blockIdx.x * blockDim.x + threadIdx.x;
    if (e < NE) {
        int p = atomicAdd(&cur_sg[sg_dst[e]], 1);
        srcs_sg[p] = sg_src[e];
        int q = atomicAdd(&cur_gs[gs_dst[e]], 1);
        srcs_gs[q] = gs_src[e];
    }
}

// ---------------- layer-1 GAT core: warp per dst, 4 heads, half output ----------------
__device__ __forceinline__ void gat1_core(int d, int lane,
                                          const int* __restrict__ off, const int* __restrict__ srcs,
                                          const float* __restrict__ xl, const float* __restrict__ xr,
                                          const float* __restrict__ att, const float* __restrict__ bias,
                                          const float* __restrict__ self, __half* __restrict__ out) {
    float attv[8], xrv[8];
    {
        const float4* pa = (const float4*)(att + lane * 8);
        const float4* pr = (const float4*)(xr + (size_t)d * HC1 + lane * 8);
        float4 a0 = pa[0], a1 = pa[1], r0 = pr[0], r1 = pr[1];
        attv[0]=a0.x; attv[1]=a0.y; attv[2]=a0.z; attv[3]=a0.w;
        attv[4]=a1.x; attv[5]=a1.y; attv[6]=a1.z; attv[7]=a1.w;
        xrv[0]=r0.x; xrv[1]=r0.y; xrv[2]=r0.z; xrv[3]=r0.w;
        xrv[4]=r1.x; xrv[5]=r1.y; xrv[6]=r1.z; xrv[7]=r1.w;
    }
    int b0 = off[d], b1 = off[d + 1];

    float m = -1e30f, den = 0.f, acc[8] = {};
    int s = (b0 < b1) ? srcs[b0] : 0;
    for (int i = b0; i < b1; i++) {
        int s_next = (i + 1 < b1) ? srcs[i + 1] : 0;
        const float4* p = (const float4*)(xl + (size_t)s * HC1 + lane * 8);
        float4 t0 = p[0], t1 = p[1];
        float t[8] = {t0.x, t0.y, t0.z, t0.w, t1.x, t1.y, t1.z, t1.w};
        float pp = 0.f;
        #pragma unroll
        for (int v = 0; v < 8; v++) {
            float g = t[v] + xrv[v];
            g = g > 0.f ? g : 0.2f * g;
            pp = fmaf(g, attv[v], pp);
        }
        pp += __shfl_xor_sync(0xFFFFFFFFu, pp, 1);
        pp += __shfl_xor_sync(0xFFFFFFFFu, pp, 2);
        pp += __shfl_xor_sync(0xFFFFFFFFu, pp, 4);
        float mn = fmaxf(m, pp);
        float sc = __expf(m - mn);
        float a  = __expf(pp - mn);
        den = den * sc + a;
        #pragma unroll
        for (int v = 0; v < 8; v++) acc[v] = fmaf(acc[v], sc, a * t[v]);
        m = mn;
        s = s_next;
    }

    float inv = 1.f / (den + 1e-16f);
    float ov[8];
    #pragma unroll
    for (int v = 0; v < 8; v++) {
        float x = acc[v] * inv + bias[lane * 8 + v];
        if (self) x += self[(size_t)d * C1 + (lane & 7) * 8 + v];
        ov[v] = x > 0.f ? x : (__expf(x) - 1.f);
    }
    __half2 hv[4];
    #pragma unroll
    for (int j = 0; j < 4; j++) hv[j] = __floats2half2_rn(ov[2 * j], ov[2 * j + 1]);
    *(uint4*)(out + (size_t)d * HC1 + lane * 8) = *(uint4*)hv;
}

__global__ void gat1_dual(const int* __restrict__ off_sg, const int* __restrict__ srcs_sg,
                          const float* __restrict__ xl_sg, const float* __restrict__ xr_sg,
                          const float* __restrict__ att_sg, const float* __restrict__ bias_sg,
                          __half* __restrict__ out_sg,
                          const int* __restrict__ off_gs, const int* __restrict__ srcs_gs,
                          const float* __restrict__ xl_gs, const float* __restrict__ xr_gs,
                          const float* __restrict__ att_gs, const float* __restrict__ bias_gs,
                          const float* __restrict__ self_gs, __half* __restrict__ out_gs) {
    int w = (blockIdx.x * blockDim.x + threadIdx.x) >> 5;
    int lane = threadIdx.x & 31;
    if (w < NG) {
        gat1_core(w, lane, off_sg, srcs_sg, xl_sg, xr_sg, att_sg, bias_sg, nullptr, out_sg);
    } else if (w < NG + NS) {
        gat1_core(w - NG, lane, off_gs, srcs_gs, xl_gs, xr_gs, att_gs, bias_gs, self_gs, out_gs);
    }
}

// ---------------- layer-3 GAT: warp per dst, head mean via shfl ----------------
__global__ void gat3_warp(const int* __restrict__ off, const int* __restrict__ srcs,
                          const float* __restrict__ xl, const float* __restrict__ xr,
                          const float* __restrict__ att, const float* __restrict__ bias3,
                          const float* __restrict__ sl3, float* __restrict__ out) {
    int d = (blockIdx.x * blockDim.x + threadIdx.x) >> 5;
    int lane = threadIdx.x & 31;
    if (d >= NS) return;

    float attv[16], xrv[16];
    {
        const float4* pa = (const float4*)(att + lane * 16);
        const float4* pr = (const float4*)(xr + (size_t)d * HC3 + lane * 16);
        #pragma unroll
        for (int q = 0; q < 4; q++) {
            float4 a = pa[q], r = pr[q];
            attv[q*4+0]=a.x; attv[q*4+1]=a.y; attv[q*4+2]=a.z; attv[q*4+3]=a.w;
            xrv[q*4+0]=r.x; xrv[q*4+1]=r.y; xrv[q*4+2]=r.z; xrv[q*4+3]=r.w;
        }
    }
    int b0 = off[d], b1 = off[d + 1];

    float m = -1e30f, den = 0.f, acc[16] = {};
    int s = (b0 < b1) ? srcs[b0] : 0;
    for (int i = b0; i < b1; i++) {
        int s_next = (i + 1 < b1) ? srcs[i + 1] : 0;
        const float4* p = (const float4*)(xl + (size_t)s * HC3 + lane * 16);
        float t[16];
        #pragma unroll
        for (int q = 0; q < 4; q++) {
            float4 tv = p[q];
            t[q*4+0]=tv.x; t[q*4+1]=tv.y; t[q*4+2]=tv.z; t[q*4+3]=tv.w;
        }
        float pp = 0.f;
        #pragma unroll
        for (int v = 0; v < 16; v++) {
            float g = t[v] + xrv[v];
            g = g > 0.f ? g : 0.2f * g;
            pp = fmaf(g, attv[v], pp);
        }
        pp += __shfl_xor_sync(0xFFFFFFFFu, pp, 1);
        pp += __shfl_xor_sync(0xFFFFFFFFu, pp, 2);
        pp += __shfl_xor_sync(0xFFFFFFFFu, pp, 4);
        float mn = fmaxf(m, pp);
        float sc = __expf(m - mn);
        float a  = __expf(pp - mn);
        den = den * sc + a;
        #pragma unroll
        for (int v = 0; v < 16; v++) acc[v] = fmaf(acc[v], sc, a * t[v]);
        m = mn;
        s = s_next;
    }

    float inv = 1.f / (den + 1e-16f);
    float ov[16];
    #pragma unroll
    for (int v = 0; v < 16; v++) {
        float hv = acc[v] * inv;
        hv += __shfl_xor_sync(0xFFFFFFFFu, hv, 8);
        hv += __shfl_xor_sync(0xFFFFFFFFu, hv, 16);
        ov[v] = 0.25f * hv;
    }
    if (lane < 8) {
        #pragma unroll
        for (int v = 0; v < 16; v++) {
            int c = lane * 16 + v;
            float x = ov[v] + bias3[c] + sl3[(size_t)d * C3 + c];
            ov[v] = x > 0.f ? x : (__expf(x) - 1.f);
        }
        float4* po = (float4*)(out + (size_t)d * C3 + lane * 16);
        #pragma unroll
        for (int q = 0; q < 4; q++)
            po[q] = make_float4(ov[q*4+0], ov[q*4+1], ov[q*4+2], ov[q*4+3]);
    }
}

// ---------------- host launch ----------------
static inline float* sym(const void* s) {
    void* p = nullptr;
    cudaGetSymbolAddress(&p, s);
    return (float*)p;
}
static inline __half* symh(const void* s) {
    void* p = nullptr;
    cudaGetSymbolAddress(&p, s);
    return (__half*)p;
}
static inline int* symi(const void* s) {
    void* p = nullptr;
    cudaGetSymbolAddress(&p, s);
    return (int*)p;
}

extern "C" void kernel_launch(void* const* d_in, const int* in_sizes, int n_in,
                              void* d_out, int out_size) {
    const float* x_sample = (const float*)d_in[0];
    const float* x_gene   = (const float*)d_in[1];
    const int*   sg_src   = (const int*)d_in[2];
    const int*   sg_dst   = (const int*)d_in[3];
    const int*   gs_src   = (const int*)d_in[4];
    const int*   gs_dst   = (const int*)d_in[5];
    const float* Wl1_sg = (const float*)d_in[6];
    const float* bl1_sg = (const float*)d_in[7];
    const float* Wr1_sg = (const float*)d_in[8];
    const float* br1_sg = (const float*)d_in[9];
    const float* att1_sg  = (const float*)d_in[10];
    const float* bias1_sg = (const float*)d_in[11];
    const float* Wl1_gs = (const float*)d_in[12];
    const float* bl1_gs = (const float*)d_in[13];
    const float* Wr1_gs = (const float*)d_in[14];
    const float* br1_gs = (const float*)d_in[15];
    const float* att1_gs  = (const float*)d_in[16];
    const float* bias1_gs = (const float*)d_in[17];
    const float* Wl3_gs = (const float*)d_in[18];
    const float* bl3_gs = (const float*)d_in[19];
    const float* Wr3_gs = (const float*)d_in[20];
    const float* br3_gs = (const float*)d_in[21];
    const float* att3_gs  = (const float*)d_in[22];
    const float* bias3_gs = (const float*)d_in[23];
    const float* sl1_W = (const float*)d_in[24];
    const float* sl1_b = (const float*)d_in[25];
    const float* sl3_W = (const float*)d_in[26];
    const float* sl3_b = (const float*)d_in[27];
    float* out = (float*)d_out;

    float* xl_sg = sym(g_xl_sg);
    float* xr_sg = sym(g_xr_sg);
    float* xl_gs = sym(g_xl_gs);
    float* xr_gs = sym(g_xr_gs);
    float* sl1 = sym(g_sl1);
    float* xl3 = sym(g_xl3);
    float* xr3 = sym(g_xr3);
    float* sl3 = sym(g_sl3);
    float* b5p = sym(g_b5p);
    __half* hxs = symh(g_hxs);
    __half* hxg = symh(g_hxg);
    __half* hWl1sg = symh(g_hWl1sg);
    __half* hWr1sg = symh(g_hWr1sg);
    __half* hWl1gs = symh(g_hWl1gs);
    __half* hWr1gs = symh(g_hWr1gs);
    __half* hw5 = symh(g_hw5);
    __half* hWl3 = symh(g_hWl3);
    __half* hWr3 = symh(g_hWr3);
    __half* hsl3W = symh(g_hsl3W);
    __half* x1h_gene = symh(g_x1h_gene);
    __half* x1h_sample = symh(g_x1h_sample);
    int* deg_sg = symi(g_deg_sg);
    int* deg_gs = symi(g_deg_gs);
    int* off_sg = symi(g_off_sg);
    int* cur_sg = symi(g_cur_sg);
    int* srcs_sg = symi(g_srcs_sg);
    int* off_gs = symi(g_off_gs);
    int* cur_gs = symi(g_cur_gs);
    int* srcs_gs = symi(g_srcs_gs);

    cudaFuncSetAttribute(gemm_batch, cudaFuncAttributeMaxDynamicSharedMemorySize, GEMM_SMEM);

    dim3 tb(256);
    int eb = (NE + 255) / 256;

    // ----- CSR build -----
    zero2_kernel<<<(NG + 255) / 256, tb>>>(deg_sg, deg_gs);
    count2_kernel<<<eb, tb>>>(sg_dst, gs_dst, deg_sg, deg_gs);
    scan2_kernel<<<2, 1024>>>(deg_sg, off_sg, cur_sg, deg_gs, off_gs, cur_gs);
    scatter2_kernel<<<eb, tb>>>(sg_src, sg_dst, cur_sg, srcs_sg,
                                gs_src, gs_dst, cur_gs, srcs_gs);

    // ----- fp16 conversion of all GEMM operands -----
    cvt_all<<<(NG * DIN + 255) / 256, tb>>>(
        x_sample, x_gene, Wl1_sg, Wr1_sg, Wl1_gs, Wr1_gs, sl1_W, sl1_b,
        Wl3_gs, Wr3_gs, sl3_W,
        hxs, hxg, hWl1sg, hWr1sg, hWl1gs, hWr1gs, hw5, b5p, hWl3, hWr3, hsl3W);

    const int MB_NS = NS / 128;            // 32
    const int MB_NG = (NG + 127) / 128;    // 157

    // ----- batch 1: all six layer-1 GEMMs -----
    {
        GemmBatch P;
        int blk = 0;
        P.seg[0] = {hxs, hWl1sg, bl1_sg, xl_sg, HC1, NS, HC1, 2, blk}; blk += 2 * MB_NS;
        P.seg[1] = {hxg, hWr1sg, br1_sg, xr_sg, HC1, NG, HC1, 2, blk}; blk += 2 * MB_NG;
        P.seg[2] = {hxg, hWl1gs, bl1_gs, xl_gs, HC1, NG, HC1, 2, blk}; blk += 2 * MB_NG;
        P.seg[3] = {hxs, hWr1gs, br1_gs, xr_gs, HC1, NS, HC1, 2, blk}; blk += 2 * MB_NS;
        P.seg[4] = {hxs, hw5,    b5p,    sl1,   128, NS, C1,  1, blk}; blk += MB_NS;
        P.seg[5] = P.seg[4];
        P.nseg = 5;
        gemm_batch<<<blk, GEMM_THREADS, GEMM_SMEM>>>(P);
    }

    // ----- both layer-1 GAT passes (write half) -----
    gat1_dual<<<((NG + NS) * 32 + 255) / 256, tb>>>(
        off_sg, srcs_sg, xl_sg, xr_sg, att1_sg, bias1_sg, x1h_gene,
        off_gs, srcs_gs, xl_gs, xr_gs, att1_gs, bias1_gs, sl1, x1h_sample);

    // ----- batch 2: all three layer-3 GEMMs -----
    {
        GemmBatch P;
        int blk = 0;
        P.seg[0] = {x1h_gene,   hWl3,  bl3_gs, xl3, HC3, NG, HC3, 4, blk}; blk += 4 * MB_NG;
        P.seg[1] = {x1h_sample, hWr3,  br3_gs, xr3, HC3, NS, HC3, 4, blk}; blk += 4 * MB_NS;
        P.seg[2] = {x1h_sample, hsl3W, sl3_b,  sl3, C3,  NS, C3,  1, blk}; blk += MB_NS;
        P.seg[3] = P.seg[2];
        P.seg[4] = P.seg[2];
        P.seg[5] = P.seg[2];
        P.nseg = 3;
        gemm_batch<<<blk, GEMM_THREADS, GEMM_SMEM>>>(P);
    }

    // ----- layer-3 GAT + epilogue -----
    gat3_warp<<<(NS * 32 + 255) / 256, tb>>>(off_gs, srcs_gs, xl3, xr3, att3_gs, bias3_gs, sl3, out);
}